// round 5
// baseline (speedup 1.0000x reference)
#include <cuda_runtime.h>
#include <math.h>

#define NN 50000
#define EE 800000
#define GG 1024
#define DD 64
#define DIN 9
#define DP 12                      // padded input dim (3 x float4)
#define NBLK ((NN + 255) / 256)    // 196 scan blocks

// ---- scratch ----
__device__ int   g_deg[NN];
__device__ float g_dinv[NN];
__device__ int   g_rowptr[NN + 1];
__device__ int   g_cursor[NN];
__device__ int   g_csrsrc[EE];
__device__ int   g_bsum[256];
__device__ float g_xs[NN * DP];    // dinv-prescaled padded input features
__device__ float g_a9[NN * DP];    // aggregated 9-dim (padded)
__device__ float g_tmp[NN * DD];   // aggregated 64-dim (GEMM input)
__device__ float g_hA[NN * DD];    // u buffers (prescaled activations)
__device__ float g_hB[NN * DD];

// ------------------- preprocessing -------------------

__global__ void k_zero_deg() {
    int i = blockIdx.x * blockDim.x + threadIdx.x;
    if (i < NN) g_deg[i] = 0;
}

__global__ void k_hist(const int* __restrict__ col) {
    int e = blockIdx.x * blockDim.x + threadIdx.x;
    if (e < EE) atomicAdd(&g_deg[col[e]], 1);
}

// phase A: per-block exclusive scan of deg; also compute dinv
__global__ void k_scanA() {
    __shared__ int sm[256];
    int t = threadIdx.x;
    int i = blockIdx.x * 256 + t;
    int v = (i < NN) ? g_deg[i] : 0;
    if (i < NN) g_dinv[i] = rsqrtf((float)v + 1.0f);  // +1 self loop
    sm[t] = v;
    __syncthreads();
#pragma unroll
    for (int off = 1; off < 256; off <<= 1) {
        int u = (t >= off) ? sm[t - off] : 0;
        __syncthreads();
        sm[t] += u;
        __syncthreads();
    }
    if (i < NN) g_rowptr[i] = sm[t] - v;
    if (t == 255) g_bsum[blockIdx.x] = sm[255];
}

// phase B: exclusive scan of block sums (one block)
__global__ void k_scanB() {
    __shared__ int sm[256];
    int t = threadIdx.x;
    int v = (t < NBLK) ? g_bsum[t] : 0;
    sm[t] = v;
    __syncthreads();
#pragma unroll
    for (int off = 1; off < 256; off <<= 1) {
        int u = (t >= off) ? sm[t - off] : 0;
        __syncthreads();
        sm[t] += u;
        __syncthreads();
    }
    g_bsum[t] = sm[t] - v;
}

// phase C: add block offsets, init cursor; also build padded prescaled xs
__global__ void k_scanC(const float* __restrict__ x) {
    int i = blockIdx.x * 256 + threadIdx.x;
    if (i < NN) {
        int r = g_rowptr[i] + g_bsum[blockIdx.x];
        g_rowptr[i] = r;
        g_cursor[i] = r;
        float di = g_dinv[i];
#pragma unroll
        for (int c = 0; c < DIN; c++) g_xs[i * DP + c] = di * x[i * DIN + c];
#pragma unroll
        for (int c = DIN; c < DP; c++) g_xs[i * DP + c] = 0.f;
    }
    if (i == 0) g_rowptr[NN] = EE;
}

__global__ void k_fill(const int* __restrict__ row, const int* __restrict__ col) {
    int e = blockIdx.x * blockDim.x + threadIdx.x;
    if (e < EE) {
        int d = col[e];
        int p = atomicAdd(&g_cursor[d], 1);
        g_csrsrc[p] = row[e];
    }
}

// ------------------- aggregation kernels -------------------

// 9-dim (padded 12) aggregation: lane-per-neighbor, warp per node.
// a9[i] = dinv[i] * (sum_nb xs[s] + xs[i])
__global__ void k_agg9(float* __restrict__ a9) {
    int warp = (blockIdx.x * blockDim.x + threadIdx.x) >> 5;
    int lid = threadIdx.x & 31;
    if (warp >= NN) return;
    int i = warp;
    int e0 = g_rowptr[i], e1 = g_rowptr[i + 1];
    const float4* xs4 = (const float4*)g_xs;
    float4 a = make_float4(0, 0, 0, 0), b = a, c = a;
    for (int e = e0 + lid; e < e1; e += 32) {
        int s = g_csrsrc[e];
        float4 v0 = xs4[s * 3 + 0];
        float4 v1 = xs4[s * 3 + 1];
        float4 v2 = xs4[s * 3 + 2];
        a.x += v0.x; a.y += v0.y; a.z += v0.z; a.w += v0.w;
        b.x += v1.x; b.y += v1.y; b.z += v1.z; b.w += v1.w;
        c.x += v2.x; c.y += v2.y; c.z += v2.z; c.w += v2.w;
    }
#pragma unroll
    for (int o = 16; o; o >>= 1) {
        a.x += __shfl_xor_sync(~0u, a.x, o); a.y += __shfl_xor_sync(~0u, a.y, o);
        a.z += __shfl_xor_sync(~0u, a.z, o); a.w += __shfl_xor_sync(~0u, a.w, o);
        b.x += __shfl_xor_sync(~0u, b.x, o); b.y += __shfl_xor_sync(~0u, b.y, o);
        b.z += __shfl_xor_sync(~0u, b.z, o); b.w += __shfl_xor_sync(~0u, b.w, o);
        c.x += __shfl_xor_sync(~0u, c.x, o);
    }
    if (lid == 0) {
        float di = g_dinv[i];
        float4 s0 = xs4[i * 3 + 0];
        float4 s1 = xs4[i * 3 + 1];
        float4 s2 = xs4[i * 3 + 2];
        float4* o4 = (float4*)a9;
        o4[i * 3 + 0] = make_float4(di * (a.x + s0.x), di * (a.y + s0.y),
                                    di * (a.z + s0.z), di * (a.w + s0.w));
        o4[i * 3 + 1] = make_float4(di * (b.x + s1.x), di * (b.y + s1.y),
                                    di * (b.z + s1.z), di * (b.w + s1.w));
        o4[i * 3 + 2] = make_float4(di * (c.x + s2.x), 0.f, 0.f, 0.f);
    }
}

// 64-dim aggregation (pure row sum of prescaled u), warp per node, float2 lanes.
// a[i] = dinv[i] * (sum_nb u[s] + u[i])
__global__ void k_agg64(const float* __restrict__ u, float* __restrict__ aout) {
    int warp = (blockIdx.x * blockDim.x + threadIdx.x) >> 5;
    int lid = threadIdx.x & 31;
    if (warp >= NN) return;
    int i = warp;
    int e = g_rowptr[i];
    int e1 = g_rowptr[i + 1];
    const float2* t2 = (const float2*)u;
    float ax = 0.f, ay = 0.f;
    for (; e + 3 < e1; e += 4) {
        int s0 = g_csrsrc[e + 0];
        int s1 = g_csrsrc[e + 1];
        int s2 = g_csrsrc[e + 2];
        int s3 = g_csrsrc[e + 3];
        float2 v0 = t2[s0 * 32 + lid];
        float2 v1 = t2[s1 * 32 + lid];
        float2 v2 = t2[s2 * 32 + lid];
        float2 v3 = t2[s3 * 32 + lid];
        ax += (v0.x + v1.x) + (v2.x + v3.x);
        ay += (v0.y + v1.y) + (v2.y + v3.y);
    }
    for (; e < e1; e++) {
        int s0 = g_csrsrc[e];
        float2 v0 = t2[s0 * 32 + lid];
        ax += v0.x;
        ay += v0.y;
    }
    float di = g_dinv[i];
    float2 self = t2[i * 32 + lid];
    float2 r;
    r.x = di * (ax + self.x);
    r.y = di * (ay + self.y);
    ((float2*)aout)[i * 32 + lid] = r;
}

// ------------------- GEMMs with fused epilogue -------------------
// out = tanh(a @ W + b), optionally prescaled by dinv[n]

// (N x 9) @ (9 x 64), a padded to 12
template <bool PRESCALE>
__global__ void k_gemm0(const float* __restrict__ a, const float* __restrict__ W0,
                        const float* __restrict__ b0, float* __restrict__ out) {
    __shared__ float sW[DIN * DD];
    __shared__ float sB[DD];
    int tid = threadIdx.x;  // 256
    for (int i = tid; i < DIN * DD; i += 256) sW[i] = W0[i];
    if (tid < DD) sB[tid] = b0[tid];
    __syncthreads();
    int local = tid >> 2;
    int j = tid & 3;
    int n = blockIdx.x * 64 + local;
    if (n >= NN) return;
    float ar[DIN];
#pragma unroll
    for (int k = 0; k < DIN; k++) ar[k] = a[n * DP + k];
    float acc[16];
#pragma unroll
    for (int d = 0; d < 16; d++) acc[d] = sB[j * 16 + d];
#pragma unroll
    for (int k = 0; k < DIN; k++) {
        float hv = ar[k];
#pragma unroll
        for (int d = 0; d < 16; d++) acc[d] += hv * sW[k * DD + j * 16 + d];
    }
    float sc = PRESCALE ? g_dinv[n] : 1.0f;
#pragma unroll
    for (int d = 0; d < 16; d++) out[n * DD + j * 16 + d] = sc * tanhf(acc[d]);
}

// (N x 64) @ (64 x 64), 64 nodes per block
template <bool PRESCALE>
__global__ void k_gemm64(const float* __restrict__ a, const float* __restrict__ W,
                         const float* __restrict__ b, float* __restrict__ out) {
    __shared__ float sW[DD * DD];
    __shared__ float sH[64 * 68];
    __shared__ float sB[DD];
    int tid = threadIdx.x;  // 256
    int nodeBase = blockIdx.x * 64;
    for (int i = tid; i < DD * DD; i += 256) sW[i] = W[i];
    if (tid < DD) sB[tid] = b[tid];
    for (int i = tid; i < 64 * DD; i += 256) {
        int r = i >> 6, c = i & 63;
        int n = nodeBase + r;
        sH[r * 68 + c] = (n < NN) ? a[n * DD + c] : 0.f;
    }
    __syncthreads();
    int local = tid >> 2;
    int j = tid & 3;
    float acc[16];
#pragma unroll
    for (int d = 0; d < 16; d++) acc[d] = sB[j * 16 + d];
    const float* hr = &sH[local * 68];
#pragma unroll
    for (int k = 0; k < DD; k++) {
        float hv = hr[k];
#pragma unroll
        for (int d = 0; d < 16; d++) acc[d] += hv * sW[k * DD + j * 16 + d];
    }
    int n = nodeBase + local;
    if (n < NN) {
        float sc = PRESCALE ? g_dinv[n] : 1.0f;
#pragma unroll
        for (int d = 0; d < 16; d++) out[n * DD + j * 16 + d] = sc * tanhf(acc[d]);
    }
}

// ------------------- pooling + head -------------------
__global__ void k_pool(const float* __restrict__ h, const float* __restrict__ Wout,
                       const float* __restrict__ bout, float* __restrict__ out) {
    int g = (blockIdx.x * blockDim.x + threadIdx.x) >> 5;
    int lid = threadIdx.x & 31;
    if (g >= GG) return;
    long long gs = (long long)g * NN;
    int start = (int)((gs + GG - 1) / GG);
    int end = (int)((gs + NN + GG - 1) / GG);
    if (end > NN) end = NN;
    const float2* h2 = (const float2*)h;
    float2 mx = make_float2(-INFINITY, -INFINITY);
    float2 sm = make_float2(0.f, 0.f);
    for (int i = start; i < end; i++) {
        float2 v = h2[i * 32 + lid];
        mx.x = fmaxf(mx.x, v.x);
        mx.y = fmaxf(mx.y, v.y);
        sm.x += v.x;
        sm.y += v.y;
    }
    int cnt = end - start; if (cnt < 1) cnt = 1;
    float inv = 1.0f / (float)cnt;
    const float2* w2 = (const float2*)Wout;
    float2 wmx = w2[lid];
    float2 wmn = w2[32 + lid];
    float v = mx.x * wmx.x + mx.y * wmx.y
            + (sm.x * inv) * wmn.x + (sm.y * inv) * wmn.y;
#pragma unroll
    for (int o = 16; o; o >>= 1) v += __shfl_down_sync(0xffffffffu, v, o);
    if (lid == 0) out[g] = v + bout[0];
}

// ------------------- launch -------------------

extern "C" void kernel_launch(void* const* d_in, const int* in_sizes, int n_in,
                              void* d_out, int out_size) {
    const float* x    = (const float*)d_in[0];
    const int*   ei   = (const int*)d_in[1];
    const float* W0   = (const float*)d_in[3];
    const float* b0   = (const float*)d_in[4];
    const float* W1   = (const float*)d_in[5];
    const float* b1   = (const float*)d_in[6];
    const float* W2   = (const float*)d_in[7];
    const float* b2   = (const float*)d_in[8];
    const float* W3   = (const float*)d_in[9];
    const float* b3   = (const float*)d_in[10];
    const float* Wout = (const float*)d_in[11];
    const float* bout = (const float*)d_in[12];
    float* out = (float*)d_out;

    const int* erow = ei;        // sources
    const int* ecol = ei + EE;   // destinations

    float *tmp, *hA, *hB, *a9;
    cudaGetSymbolAddress((void**)&tmp, g_tmp);
    cudaGetSymbolAddress((void**)&hA, g_hA);
    cudaGetSymbolAddress((void**)&hB, g_hB);
    cudaGetSymbolAddress((void**)&a9, g_a9);

    int eB = (EE + 255) / 256;
    int gB = (NN + 63) / 64;
    int aB = (NN + 7) / 8;       // warp-per-node kernels, 8 warps/block
    int pB = (GG * 32 + 255) / 256;

    k_zero_deg<<<NBLK, 256>>>();
    k_hist<<<eB, 256>>>(ecol);
    k_scanA<<<NBLK, 256>>>();
    k_scanB<<<1, 256>>>();
    k_scanC<<<NBLK, 256>>>(x);
    k_fill<<<eB, 256>>>(erow, ecol);

    // layer 0: aggregate in 9-dim, then GEMM0 (+bias+tanh+prescale)
    k_agg9<<<aB, 256>>>(a9);
    k_gemm0<true><<<gB, 256>>>(a9, W0, b0, hA);

    // layers 1..2: aggregate u -> GEMM (+prescale)
    k_agg64<<<aB, 256>>>(hA, tmp);
    k_gemm64<true><<<gB, 256>>>(tmp, W1, b1, hB);

    k_agg64<<<aB, 256>>>(hB, tmp);
    k_gemm64<true><<<gB, 256>>>(tmp, W2, b2, hA);

    // layer 3: final GEMM without prescale (h3 = tanh(a W3 + b3))
    k_agg64<<<aB, 256>>>(hA, tmp);
    k_gemm64<false><<<gB, 256>>>(tmp, W3, b3, hB);

    k_pool<<<pB, 256>>>(hB, Wout, bout, out);
}

// round 6
// speedup vs baseline: 1.1143x; 1.1143x over previous
#include <cuda_runtime.h>
#include <cuda_fp16.h>
#include <math.h>

#define NN 50000
#define EE 800000
#define GG 1024
#define DD 64
#define DIN 9
#define DP 12
#define NBLK ((NN + 255) / 256)   // 196

// ---- scratch ----
__device__ int   g_deg[NN];
__device__ float g_dinv[NN];
__device__ int   g_rowptr[NN + 1];
__device__ int   g_cursor[NN];
__device__ int   g_csrsrc[EE];
__device__ unsigned long long g_blkDesc[NBLK];  // (val<<2)|flag ; 1=agg, 2=prefix
__device__ float g_xs[NN * DP];    // dinv-prescaled padded input features
__device__ float g_hA[NN * DD];    // activation buffers (used as half or float)
__device__ float g_hB[NN * DD];

// ------------------- preprocessing -------------------

__global__ void k_zero() {
    int i = blockIdx.x * blockDim.x + threadIdx.x;
    if (i < NN) g_deg[i] = 0;
    if (i < NBLK) g_blkDesc[i] = 0ULL;
}

__global__ void k_hist(const int* __restrict__ col) {
    int e = blockIdx.x * blockDim.x + threadIdx.x;
    if (e < EE) atomicAdd(&g_deg[col[e]], 1);
}

// single-pass scan (decoupled lookback) + dinv + prescaled padded xs
__global__ void k_scan(const float* __restrict__ x) {
    __shared__ int wsum[8];
    __shared__ int sprefix;
    int b = blockIdx.x, t = threadIdx.x;
    int i = b * 256 + t;
    int lane = t & 31, w = t >> 5;
    int v = (i < NN) ? g_deg[i] : 0;
    // warp inclusive scan
    int s = v;
#pragma unroll
    for (int o = 1; o < 32; o <<= 1) {
        int u = __shfl_up_sync(~0u, s, o);
        if (lane >= o) s += u;
    }
    if (lane == 31) wsum[w] = s;
    __syncthreads();
    if (w == 0) {
        int ws = (lane < 8) ? wsum[lane] : 0;
#pragma unroll
        for (int o = 1; o < 8; o <<= 1) {
            int u = __shfl_up_sync(0xffu, ws, o);
            if (lane >= o) ws += u;
        }
        if (lane < 8) wsum[lane] = ws;
    }
    __syncthreads();
    int total = wsum[7];
    if (t == 0) {
        if (b == 0) {
            atomicExch(&g_blkDesc[0], ((unsigned long long)total << 2) | 2ULL);
            sprefix = 0;
        } else {
            atomicExch(&g_blkDesc[b], ((unsigned long long)total << 2) | 1ULL);
            int run = 0;
            for (int j = b - 1; j >= 0; j--) {
                unsigned long long d;
                do { d = *((volatile unsigned long long*)&g_blkDesc[j]); } while ((d & 3ULL) == 0ULL);
                run += (int)(d >> 2);
                if ((d & 3ULL) == 2ULL) break;
            }
            sprefix = run;
            atomicExch(&g_blkDesc[b], ((unsigned long long)(total + run) << 2) | 2ULL);
        }
    }
    __syncthreads();
    int excl = sprefix + (w > 0 ? wsum[w - 1] : 0) + (s - v);
    if (i < NN) {
        g_rowptr[i] = excl;
        g_cursor[i] = excl;
        float di = rsqrtf((float)v + 1.0f);  // +1 self loop
        g_dinv[i] = di;
#pragma unroll
        for (int c = 0; c < DIN; c++) g_xs[i * DP + c] = di * x[i * DIN + c];
#pragma unroll
        for (int c = DIN; c < DP; c++) g_xs[i * DP + c] = 0.f;
    }
    if (i == 0) g_rowptr[NN] = EE;
}

__global__ void k_fill(const int* __restrict__ row, const int* __restrict__ col) {
    int e = blockIdx.x * blockDim.x + threadIdx.x;
    if (e < EE) {
        int d = col[e];
        int p = atomicAdd(&g_cursor[d], 1);
        g_csrsrc[p] = row[e];
    }
}

// ------------------- fused layer 0: agg(9-dim) + GEMM0 + tanh + prescale -> half -------------------

__global__ void k_layer0(const float* __restrict__ W0, const float* __restrict__ b0,
                         __half2* __restrict__ uout) {
    __shared__ float sW[DIN * DD];
    __shared__ float sH[64 * DP];
    __shared__ float sB[DD];
    int tid = threadIdx.x;  // 256
    int nodeBase = blockIdx.x * 64;
    for (int i = tid; i < DIN * DD; i += 256) sW[i] = W0[i];
    if (tid < DD) sB[tid] = b0[tid];
    int w = tid >> 5, lid = tid & 31;
#pragma unroll
    for (int k = 0; k < 8; k++) {
        int local = w * 8 + k;
        int node = nodeBase + local;
        float a = 0.f;
        if (node < NN && lid < DP) {
            int e = g_rowptr[node], e1 = g_rowptr[node + 1];
            for (; e + 3 < e1; e += 4) {
                int s0 = g_csrsrc[e + 0];
                int s1 = g_csrsrc[e + 1];
                int s2 = g_csrsrc[e + 2];
                int s3 = g_csrsrc[e + 3];
                a += (g_xs[s0 * DP + lid] + g_xs[s1 * DP + lid])
                   + (g_xs[s2 * DP + lid] + g_xs[s3 * DP + lid]);
            }
            for (; e < e1; e++) a += g_xs[g_csrsrc[e] * DP + lid];
            float di = g_dinv[node];
            a = di * (a + g_xs[node * DP + lid]);
        }
        if (lid < DP) sH[local * DP + lid] = a;
    }
    __syncthreads();
    int local = tid >> 2, j = tid & 3;
    float acc[16];
#pragma unroll
    for (int d = 0; d < 16; d++) acc[d] = sB[j * 16 + d];
    const float* hr = &sH[local * DP];
#pragma unroll
    for (int k = 0; k < DIN; k++) {
        float hv = hr[k];
#pragma unroll
        for (int d = 0; d < 16; d++) acc[d] += hv * sW[k * DD + j * 16 + d];
    }
    int n = nodeBase + local;
    if (n < NN) {
        float sc = g_dinv[n];
#pragma unroll
        for (int d = 0; d < 16; d += 2)
            uout[n * 32 + j * 8 + (d >> 1)] =
                __floats2half2_rn(sc * tanhf(acc[d]), sc * tanhf(acc[d + 1]));
    }
}

// ------------------- fused layer: agg(64, half in) + GEMM64 + tanh (+prescale) -------------------

template <bool OUT_HALF, bool PRESCALE>
__global__ void k_layer(const __half2* __restrict__ uin, const float* __restrict__ W,
                        const float* __restrict__ bias, void* __restrict__ uout) {
    __shared__ float sW[DD * DD];   // 16 KB
    __shared__ float sH[64 * 68];   // 17.4 KB
    __shared__ float sB[DD];
    int tid = threadIdx.x;  // 256
    int nodeBase = blockIdx.x * 64;
    for (int i = tid; i < DD * DD; i += 256) sW[i] = W[i];
    if (tid < DD) sB[tid] = bias[tid];
    int w = tid >> 5, lid = tid & 31;
#pragma unroll
    for (int k = 0; k < 8; k++) {
        int local = w * 8 + k;
        int node = nodeBase + local;
        float ax = 0.f, ay = 0.f;
        if (node < NN) {
            int e = g_rowptr[node], e1 = g_rowptr[node + 1];
            for (; e + 3 < e1; e += 4) {
                int s0 = g_csrsrc[e + 0];
                int s1 = g_csrsrc[e + 1];
                int s2 = g_csrsrc[e + 2];
                int s3 = g_csrsrc[e + 3];
                float2 f0 = __half22float2(uin[s0 * 32 + lid]);
                float2 f1 = __half22float2(uin[s1 * 32 + lid]);
                float2 f2 = __half22float2(uin[s2 * 32 + lid]);
                float2 f3 = __half22float2(uin[s3 * 32 + lid]);
                ax += (f0.x + f1.x) + (f2.x + f3.x);
                ay += (f0.y + f1.y) + (f2.y + f3.y);
            }
            for (; e < e1; e++) {
                float2 f = __half22float2(uin[g_csrsrc[e] * 32 + lid]);
                ax += f.x;
                ay += f.y;
            }
            float2 self = __half22float2(uin[node * 32 + lid]);
            float di = g_dinv[node];
            ax = di * (ax + self.x);
            ay = di * (ay + self.y);
        }
        sH[local * 68 + 2 * lid] = ax;
        sH[local * 68 + 2 * lid + 1] = ay;
    }
    __syncthreads();
    int local = tid >> 2, j = tid & 3;
    float acc[16];
#pragma unroll
    for (int d = 0; d < 16; d++) acc[d] = sB[j * 16 + d];
    const float* hr = &sH[local * 68];
#pragma unroll
    for (int k = 0; k < DD; k++) {
        float hv = hr[k];
#pragma unroll
        for (int d = 0; d < 16; d++) acc[d] += hv * sW[k * DD + j * 16 + d];
    }
    int n = nodeBase + local;
    if (n < NN) {
        if (OUT_HALF) {
            float sc = PRESCALE ? g_dinv[n] : 1.0f;
            __half2* o2 = (__half2*)uout;
#pragma unroll
            for (int d = 0; d < 16; d += 2)
                o2[n * 32 + j * 8 + (d >> 1)] =
                    __floats2half2_rn(sc * tanhf(acc[d]), sc * tanhf(acc[d + 1]));
        } else {
            float* o = (float*)uout;
#pragma unroll
            for (int d = 0; d < 16; d++) o[n * DD + j * 16 + d] = tanhf(acc[d]);
        }
    }
}

// ------------------- pooling + head -------------------
__global__ void k_pool(const float* __restrict__ h, const float* __restrict__ Wout,
                       const float* __restrict__ bout, float* __restrict__ out) {
    int g = (blockIdx.x * blockDim.x + threadIdx.x) >> 5;
    int lid = threadIdx.x & 31;
    if (g >= GG) return;
    long long gs = (long long)g * NN;
    int start = (int)((gs + GG - 1) / GG);
    int end = (int)((gs + NN + GG - 1) / GG);
    if (end > NN) end = NN;
    const float2* h2 = (const float2*)h;
    float2 mx = make_float2(-INFINITY, -INFINITY);
    float2 sm = make_float2(0.f, 0.f);
    for (int i = start; i < end; i++) {
        float2 v = h2[i * 32 + lid];
        mx.x = fmaxf(mx.x, v.x);
        mx.y = fmaxf(mx.y, v.y);
        sm.x += v.x;
        sm.y += v.y;
    }
    int cnt = end - start; if (cnt < 1) cnt = 1;
    float inv = 1.0f / (float)cnt;
    const float2* w2 = (const float2*)Wout;
    float2 wmx = w2[lid];
    float2 wmn = w2[32 + lid];
    float v = mx.x * wmx.x + mx.y * wmx.y
            + (sm.x * inv) * wmn.x + (sm.y * inv) * wmn.y;
#pragma unroll
    for (int o = 16; o; o >>= 1) v += __shfl_down_sync(0xffffffffu, v, o);
    if (lid == 0) out[g] = v + bout[0];
}

// ------------------- launch -------------------

extern "C" void kernel_launch(void* const* d_in, const int* in_sizes, int n_in,
                              void* d_out, int out_size) {
    const float* x    = (const float*)d_in[0];
    const int*   ei   = (const int*)d_in[1];
    const float* W0   = (const float*)d_in[3];
    const float* b0   = (const float*)d_in[4];
    const float* W1   = (const float*)d_in[5];
    const float* b1   = (const float*)d_in[6];
    const float* W2   = (const float*)d_in[7];
    const float* b2   = (const float*)d_in[8];
    const float* W3   = (const float*)d_in[9];
    const float* b3   = (const float*)d_in[10];
    const float* Wout = (const float*)d_in[11];
    const float* bout = (const float*)d_in[12];
    float* out = (float*)d_out;

    const int* erow = ei;        // sources
    const int* ecol = ei + EE;   // destinations

    float *hA, *hB;
    cudaGetSymbolAddress((void**)&hA, g_hA);
    cudaGetSymbolAddress((void**)&hB, g_hB);

    int eB = (EE + 255) / 256;
    int gB = (NN + 63) / 64;
    int pB = (GG * 32 + 255) / 256;

    k_zero<<<NBLK, 256>>>();
    k_hist<<<eB, 256>>>(ecol);
    k_scan<<<NBLK, 256>>>(x);
    k_fill<<<eB, 256>>>(erow, ecol);

    k_layer0<<<gB, 256>>>(W0, b0, (__half2*)hA);
    k_layer<true, true><<<gB, 256>>>((const __half2*)hA, W1, b1, hB);
    k_layer<true, true><<<gB, 256>>>((const __half2*)hB, W2, b2, hA);
    k_layer<false, false><<<gB, 256>>>((const __half2*)hA, W3, b3, hB);

    k_pool<<<pB, 256>>>(hB, Wout, bout, out);
}

// round 7
// speedup vs baseline: 1.9413x; 1.7422x over previous
#include <cuda_runtime.h>
#include <cuda_fp16.h>
#include <math.h>

#define NN 50000
#define EE 800000
#define GG 1024
#define DD 64
#define DIN 9
#define DP 12
#define NBLK ((NN + 255) / 256)   // 196

// ---- scratch ----
__device__ int   g_deg[NN];        // must be all-zero at kernel_launch entry;
                                   // static-init zero + re-zeroed in k_fill each call
__device__ float g_dinv[NN];
__device__ int   g_rowptr[NN + 1];
__device__ int   g_cursor[NN];
__device__ int   g_csrsrc[EE];
__device__ unsigned long long g_blkDesc[NBLK];  // zeroed in k_hist each call
__device__ float g_xs[NN * DP];
__device__ float g_hA[NN * DD];
__device__ float g_hB[NN * DD];

__device__ __forceinline__ float tanh_a(float x) {
    float y;
    asm("tanh.approx.f32 %0, %1;" : "=f"(y) : "f"(x));
    return y;
}

// ------------------- preprocessing -------------------

// histogram of destination degrees; also zero the scan descriptors for this call
__global__ void k_hist(const int* __restrict__ col) {
    int e = blockIdx.x * blockDim.x + threadIdx.x;
    if (e < NBLK) g_blkDesc[e] = 0ULL;
    if (e < EE) atomicAdd(&g_deg[col[e]], 1);
}

// single-pass scan (decoupled lookback) + dinv + prescaled padded xs
__global__ void k_scan(const float* __restrict__ x) {
    __shared__ int wsum[8];
    __shared__ int sprefix;
    int b = blockIdx.x, t = threadIdx.x;
    int i = b * 256 + t;
    int lane = t & 31, w = t >> 5;
    int v = (i < NN) ? g_deg[i] : 0;
    int s = v;
#pragma unroll
    for (int o = 1; o < 32; o <<= 1) {
        int u = __shfl_up_sync(~0u, s, o);
        if (lane >= o) s += u;
    }
    if (lane == 31) wsum[w] = s;
    __syncthreads();
    if (w == 0) {
        int ws = (lane < 8) ? wsum[lane] : 0;
#pragma unroll
        for (int o = 1; o < 8; o <<= 1) {
            int u = __shfl_up_sync(0xffu, ws, o);
            if (lane >= o) ws += u;
        }
        if (lane < 8) wsum[lane] = ws;
    }
    __syncthreads();
    int total = wsum[7];
    if (t == 0) {
        if (b == 0) {
            atomicExch(&g_blkDesc[0], ((unsigned long long)total << 2) | 2ULL);
            sprefix = 0;
        } else {
            atomicExch(&g_blkDesc[b], ((unsigned long long)total << 2) | 1ULL);
            int run = 0;
            for (int j = b - 1; j >= 0; j--) {
                unsigned long long d;
                do { d = *((volatile unsigned long long*)&g_blkDesc[j]); } while ((d & 3ULL) == 0ULL);
                run += (int)(d >> 2);
                if ((d & 3ULL) == 2ULL) break;
            }
            sprefix = run;
            atomicExch(&g_blkDesc[b], ((unsigned long long)(total + run) << 2) | 2ULL);
        }
    }
    __syncthreads();
    int excl = sprefix + (w > 0 ? wsum[w - 1] : 0) + (s - v);
    if (i < NN) {
        g_rowptr[i] = excl;
        g_cursor[i] = excl;
        float di = rsqrtf((float)v + 1.0f);  // +1 self loop
        g_dinv[i] = di;
#pragma unroll
        for (int c = 0; c < DIN; c++) g_xs[i * DP + c] = di * x[i * DIN + c];
#pragma unroll
        for (int c = DIN; c < DP; c++) g_xs[i * DP + c] = 0.f;
    }
    if (i == 0) g_rowptr[NN] = EE;
}

// scatter sources into CSR; also restore g_deg = 0 for the next call
// (g_deg's last reader is k_scan, which precedes this kernel in stream order)
__global__ void k_fill(const int* __restrict__ row, const int* __restrict__ col) {
    int e = blockIdx.x * blockDim.x + threadIdx.x;
    if (e < NN) g_deg[e] = 0;
    if (e < EE) {
        int d = col[e];
        int p = atomicAdd(&g_cursor[d], 1);
        g_csrsrc[p] = row[e];
    }
}

// ------------------- fused layer 0: agg(9-dim) + GEMM0 + tanh + prescale -> half -------------------

__global__ void __launch_bounds__(512) k_layer0(const float* __restrict__ W0,
                                                const float* __restrict__ b0,
                                                __half2* __restrict__ uout) {
    __shared__ float sW[DIN * DD];
    __shared__ float sHT[DP][68];   // transposed: [feature][node]
    __shared__ float sB[DD];
    __shared__ float sDI[64];
    int tid = threadIdx.x;
    int nodeBase = blockIdx.x * 64;
    for (int i = tid; i < DIN * DD; i += 512) sW[i] = W0[i];
    if (tid < DD) sB[tid] = b0[tid];
    int w = tid >> 5, lid = tid & 31;
#pragma unroll
    for (int q = 0; q < 4; q++) {
        int local = w * 4 + q;
        int node = nodeBase + local;
        float a = 0.f, di = 0.f;
        if (node < NN) {
            if (lid < DP) {
                int e = g_rowptr[node], e1 = g_rowptr[node + 1];
                while (e < e1 && (e & 3)) { a += g_xs[g_csrsrc[e] * DP + lid]; e++; }
                for (; e + 4 <= e1; e += 4) {
                    int4 s = *reinterpret_cast<const int4*>(&g_csrsrc[e]);
                    a += (g_xs[s.x * DP + lid] + g_xs[s.y * DP + lid])
                       + (g_xs[s.z * DP + lid] + g_xs[s.w * DP + lid]);
                }
                for (; e < e1; e++) a += g_xs[g_csrsrc[e] * DP + lid];
            }
            di = g_dinv[node];
            if (lid < DP) a = di * (a + g_xs[node * DP + lid]);
        }
        if (lid < DP) sHT[lid][local] = a;
        if (lid == 0) sDI[local] = di;
    }
    __syncthreads();
    int dq = tid & 31, nq = tid >> 5;   // cols (2dq,2dq+1), nodes 4nq..4nq+3
    float acc[4][2];
#pragma unroll
    for (int i = 0; i < 4; i++) { acc[i][0] = sB[2 * dq]; acc[i][1] = sB[2 * dq + 1]; }
#pragma unroll
    for (int k = 0; k < DIN; k++) {
        float4 h4 = *reinterpret_cast<const float4*>(&sHT[k][4 * nq]);
        float2 w2 = *reinterpret_cast<const float2*>(&sW[k * DD + 2 * dq]);
        acc[0][0] += h4.x * w2.x; acc[0][1] += h4.x * w2.y;
        acc[1][0] += h4.y * w2.x; acc[1][1] += h4.y * w2.y;
        acc[2][0] += h4.z * w2.x; acc[2][1] += h4.z * w2.y;
        acc[3][0] += h4.w * w2.x; acc[3][1] += h4.w * w2.y;
    }
#pragma unroll
    for (int i = 0; i < 4; i++) {
        int n = nodeBase + 4 * nq + i;
        if (n < NN) {
            float sc = sDI[4 * nq + i];
            uout[n * 32 + dq] = __floats2half2_rn(sc * tanh_a(acc[i][0]),
                                                  sc * tanh_a(acc[i][1]));
        }
    }
}

// ------------------- fused layer: agg(64, half in) + GEMM64 + tanh (+prescale) -------------------

template <bool OUT_HALF, bool PRESCALE>
__global__ void __launch_bounds__(512) k_layer(const __half2* __restrict__ uin,
                                               const float* __restrict__ W,
                                               const float* __restrict__ bias,
                                               void* __restrict__ uout) {
    __shared__ float sW[DD * DD];   // 16 KB
    __shared__ float sHT[DD][68];   // transposed agg tile, 17.4 KB
    __shared__ float sB[DD];
    __shared__ float sDI[64];
    int tid = threadIdx.x;
    int nodeBase = blockIdx.x * 64;
    for (int i = tid; i < DD * DD; i += 512) sW[i] = W[i];
    if (tid < DD) sB[tid] = bias[tid];
    int w = tid >> 5, lid = tid & 31;
#pragma unroll
    for (int q = 0; q < 4; q++) {
        int local = w * 4 + q;
        int node = nodeBase + local;
        float ax = 0.f, ay = 0.f, di = 0.f;
        if (node < NN) {
            int e = g_rowptr[node], e1 = g_rowptr[node + 1];
            while (e < e1 && (e & 3)) {
                float2 f = __half22float2(uin[g_csrsrc[e] * 32 + lid]);
                ax += f.x; ay += f.y; e++;
            }
            for (; e + 4 <= e1; e += 4) {
                int4 s = *reinterpret_cast<const int4*>(&g_csrsrc[e]);
                float2 f0 = __half22float2(uin[s.x * 32 + lid]);
                float2 f1 = __half22float2(uin[s.y * 32 + lid]);
                float2 f2 = __half22float2(uin[s.z * 32 + lid]);
                float2 f3 = __half22float2(uin[s.w * 32 + lid]);
                ax += (f0.x + f1.x) + (f2.x + f3.x);
                ay += (f0.y + f1.y) + (f2.y + f3.y);
            }
            for (; e < e1; e++) {
                float2 f = __half22float2(uin[g_csrsrc[e] * 32 + lid]);
                ax += f.x; ay += f.y;
            }
            float2 self = __half22float2(uin[node * 32 + lid]);
            di = g_dinv[node];
            ax = di * (ax + self.x);
            ay = di * (ay + self.y);
        }
        sHT[2 * lid][local] = ax;
        sHT[2 * lid + 1][local] = ay;
        if (lid == 0) sDI[local] = di;
    }
    __syncthreads();
    int dq = tid & 31, nq = tid >> 5;
    float acc[4][2];
#pragma unroll
    for (int i = 0; i < 4; i++) { acc[i][0] = sB[2 * dq]; acc[i][1] = sB[2 * dq + 1]; }
#pragma unroll
    for (int k = 0; k < DD; k++) {
        float4 h4 = *reinterpret_cast<const float4*>(&sHT[k][4 * nq]);
        float2 w2 = *reinterpret_cast<const float2*>(&sW[k * DD + 2 * dq]);
        acc[0][0] += h4.x * w2.x; acc[0][1] += h4.x * w2.y;
        acc[1][0] += h4.y * w2.x; acc[1][1] += h4.y * w2.y;
        acc[2][0] += h4.z * w2.x; acc[2][1] += h4.z * w2.y;
        acc[3][0] += h4.w * w2.x; acc[3][1] += h4.w * w2.y;
    }
#pragma unroll
    for (int i = 0; i < 4; i++) {
        int n = nodeBase + 4 * nq + i;
        if (n < NN) {
            if (OUT_HALF) {
                float sc = PRESCALE ? sDI[4 * nq + i] : 1.0f;
                ((__half2*)uout)[n * 32 + dq] =
                    __floats2half2_rn(sc * tanh_a(acc[i][0]), sc * tanh_a(acc[i][1]));
            } else {
                ((float2*)uout)[n * 32 + dq] =
                    make_float2(tanh_a(acc[i][0]), tanh_a(acc[i][1]));
            }
        }
    }
}

// ------------------- pooling + head -------------------
__global__ void k_pool(const float* __restrict__ h, const float* __restrict__ Wout,
                       const float* __restrict__ bout, float* __restrict__ out) {
    int g = (blockIdx.x * blockDim.x + threadIdx.x) >> 5;
    int lid = threadIdx.x & 31;
    if (g >= GG) return;
    long long gs = (long long)g * NN;
    int start = (int)((gs + GG - 1) / GG);
    int end = (int)((gs + NN + GG - 1) / GG);
    if (end > NN) end = NN;
    const float2* h2 = (const float2*)h;
    float2 mx = make_float2(-INFINITY, -INFINITY);
    float2 sm = make_float2(0.f, 0.f);
    for (int i = start; i < end; i++) {
        float2 v = h2[i * 32 + lid];
        mx.x = fmaxf(mx.x, v.x);
        mx.y = fmaxf(mx.y, v.y);
        sm.x += v.x;
        sm.y += v.y;
    }
    int cnt = end - start; if (cnt < 1) cnt = 1;
    float inv = 1.0f / (float)cnt;
    const float2* w2 = (const float2*)Wout;
    float2 wmx = w2[lid];
    float2 wmn = w2[32 + lid];
    float v = mx.x * wmx.x + mx.y * wmx.y
            + (sm.x * inv) * wmn.x + (sm.y * inv) * wmn.y;
#pragma unroll
    for (int o = 16; o; o >>= 1) v += __shfl_down_sync(0xffffffffu, v, o);
    if (lid == 0) out[g] = v + bout[0];
}

// ------------------- launch -------------------

extern "C" void kernel_launch(void* const* d_in, const int* in_sizes, int n_in,
                              void* d_out, int out_size) {
    const float* x    = (const float*)d_in[0];
    const int*   ei   = (const int*)d_in[1];
    const float* W0   = (const float*)d_in[3];
    const float* b0   = (const float*)d_in[4];
    const float* W1   = (const float*)d_in[5];
    const float* b1   = (const float*)d_in[6];
    const float* W2   = (const float*)d_in[7];
    const float* b2   = (const float*)d_in[8];
    const float* W3   = (const float*)d_in[9];
    const float* b3   = (const float*)d_in[10];
    const float* Wout = (const float*)d_in[11];
    const float* bout = (const float*)d_in[12];
    float* out = (float*)d_out;

    const int* erow = ei;        // sources
    const int* ecol = ei + EE;   // destinations

    float *hA, *hB;
    cudaGetSymbolAddress((void**)&hA, g_hA);
    cudaGetSymbolAddress((void**)&hB, g_hB);

    int eB = (EE + 255) / 256;
    int gB = (NN + 63) / 64;     // 782 layer blocks
    int pB = (GG * 32 + 255) / 256;

    k_hist<<<eB, 256>>>(ecol);
    k_scan<<<NBLK, 256>>>(x);
    k_fill<<<eB, 256>>>(erow, ecol);

    k_layer0<<<gB, 512>>>(W0, b0, (__half2*)hA);
    k_layer<true, true><<<gB, 512>>>((const __half2*)hA, W1, b1, hB);
    k_layer<true, true><<<gB, 512>>>((const __half2*)hB, W2, b2, hA);
    k_layer<false, false><<<gB, 512>>>((const __half2*)hA, W3, b3, hB);

    k_pool<<<pB, 256>>>(hB, Wout, bout, out);
}

// round 8
// speedup vs baseline: 2.0713x; 1.0670x over previous
#include <cuda_runtime.h>
#include <cuda_fp16.h>
#include <math.h>

#define NN 50000
#define EE 800000
#define GG 1024
#define DD 64
#define DIN 9
#define DP 12
#define NBLK ((NN + 255) / 256)   // 196

// ---- scratch ----
__device__ int   g_deg[NN];        // all-zero at entry; re-zeroed in k_fill each call
__device__ float g_dinv[NN];
__device__ int   g_rowptr[NN + 1];
__device__ int   g_cursor[NN];
__device__ int   g_csrsrc[EE];
__device__ unsigned long long g_blkDesc[NBLK];  // zeroed in k_hist each call
__device__ float g_xs[NN * DP];
__device__ float g_hA[NN * DD];
__device__ float g_hB[NN * DD];

__device__ __forceinline__ float tanh_a(float x) {
    float y;
    asm("tanh.approx.f32 %0, %1;" : "=f"(y) : "f"(x));
    return y;
}

// ------------------- preprocessing -------------------

// histogram of destination degrees (4 edges/thread); zero scan descriptors
__global__ void k_hist(const int* __restrict__ col) {
    int i = blockIdx.x * blockDim.x + threadIdx.x;
    if (i < NBLK) g_blkDesc[i] = 0ULL;
    if (i * 4 < EE) {
        int4 c = reinterpret_cast<const int4*>(col)[i];
        atomicAdd(&g_deg[c.x], 1);
        atomicAdd(&g_deg[c.y], 1);
        atomicAdd(&g_deg[c.z], 1);
        atomicAdd(&g_deg[c.w], 1);
    }
}

// single-pass scan (decoupled lookback) + dinv + prescaled padded xs
__global__ void k_scan(const float* __restrict__ x) {
    __shared__ int wsum[8];
    __shared__ int sprefix;
    int b = blockIdx.x, t = threadIdx.x;
    int i = b * 256 + t;
    int lane = t & 31, w = t >> 5;
    int v = (i < NN) ? g_deg[i] : 0;
    int s = v;
#pragma unroll
    for (int o = 1; o < 32; o <<= 1) {
        int u = __shfl_up_sync(~0u, s, o);
        if (lane >= o) s += u;
    }
    if (lane == 31) wsum[w] = s;
    __syncthreads();
    if (w == 0) {
        int ws = (lane < 8) ? wsum[lane] : 0;
#pragma unroll
        for (int o = 1; o < 8; o <<= 1) {
            int u = __shfl_up_sync(0xffu, ws, o);
            if (lane >= o) ws += u;
        }
        if (lane < 8) wsum[lane] = ws;
    }
    __syncthreads();
    int total = wsum[7];
    if (t == 0) {
        if (b == 0) {
            atomicExch(&g_blkDesc[0], ((unsigned long long)total << 2) | 2ULL);
            sprefix = 0;
        } else {
            atomicExch(&g_blkDesc[b], ((unsigned long long)total << 2) | 1ULL);
            int run = 0;
            for (int j = b - 1; j >= 0; j--) {
                unsigned long long d;
                do { d = *((volatile unsigned long long*)&g_blkDesc[j]); } while ((d & 3ULL) == 0ULL);
                run += (int)(d >> 2);
                if ((d & 3ULL) == 2ULL) break;
            }
            sprefix = run;
            atomicExch(&g_blkDesc[b], ((unsigned long long)(total + run) << 2) | 2ULL);
        }
    }
    __syncthreads();
    int excl = sprefix + (w > 0 ? wsum[w - 1] : 0) + (s - v);
    if (i < NN) {
        g_rowptr[i] = excl;
        g_cursor[i] = excl;
        float di = rsqrtf((float)v + 1.0f);  // +1 self loop
        g_dinv[i] = di;
#pragma unroll
        for (int c = 0; c < DIN; c++) g_xs[i * DP + c] = di * x[i * DIN + c];
#pragma unroll
        for (int c = DIN; c < DP; c++) g_xs[i * DP + c] = 0.f;
    }
    if (i == 0) g_rowptr[NN] = EE;
}

// scatter sources into CSR (4 edges/thread); restore g_deg = 0 for next call
__global__ void k_fill(const int* __restrict__ row, const int* __restrict__ col) {
    int i = blockIdx.x * blockDim.x + threadIdx.x;
    if (i < NN) g_deg[i] = 0;
    if (i * 4 < EE) {
        int4 r = reinterpret_cast<const int4*>(row)[i];
        int4 c = reinterpret_cast<const int4*>(col)[i];
        g_csrsrc[atomicAdd(&g_cursor[c.x], 1)] = r.x;
        g_csrsrc[atomicAdd(&g_cursor[c.y], 1)] = r.y;
        g_csrsrc[atomicAdd(&g_cursor[c.z], 1)] = r.z;
        g_csrsrc[atomicAdd(&g_cursor[c.w], 1)] = r.w;
    }
}

// ------------------- fused layer 0: agg(9-dim) + GEMM0 + tanh + prescale -> half -------------------
// gather: 2 nodes per warp-pass (half-warps), lanes 0-11 / 16-27 active

__global__ void __launch_bounds__(512) k_layer0(const float* __restrict__ W0,
                                                const float* __restrict__ b0,
                                                __half2* __restrict__ uout) {
    __shared__ float sW[DIN * DD];
    __shared__ float sHT[DP][68];   // transposed: [feature][node]
    __shared__ float sB[DD];
    __shared__ float sDI[64];
    int tid = threadIdx.x;
    int nodeBase = blockIdx.x * 64;
    for (int i = tid; i < DIN * DD; i += 512) sW[i] = W0[i];
    if (tid < DD) sB[tid] = b0[tid];
    int w = tid >> 5, lid = tid & 31;
    int sub = lid >> 4;       // 0/1: which node of the pair
    int fl = lid & 15;        // feature lane, active < DP
#pragma unroll
    for (int pass = 0; pass < 2; pass++) {
        int local = w * 4 + pass * 2 + sub;
        int node = nodeBase + local;
        float a = 0.f, di = 0.f;
        if (node < NN) {
            di = g_dinv[node];
            if (fl < DP) {
                int e = g_rowptr[node], e1 = g_rowptr[node + 1];
                while (e < e1 && (e & 3)) { a += g_xs[g_csrsrc[e] * DP + fl]; e++; }
                for (; e + 8 <= e1; e += 8) {
                    int4 sa = *reinterpret_cast<const int4*>(&g_csrsrc[e]);
                    int4 sb = *reinterpret_cast<const int4*>(&g_csrsrc[e + 4]);
                    a += (g_xs[sa.x * DP + fl] + g_xs[sa.y * DP + fl])
                       + (g_xs[sa.z * DP + fl] + g_xs[sa.w * DP + fl])
                       + (g_xs[sb.x * DP + fl] + g_xs[sb.y * DP + fl])
                       + (g_xs[sb.z * DP + fl] + g_xs[sb.w * DP + fl]);
                }
                for (; e + 4 <= e1; e += 4) {
                    int4 sa = *reinterpret_cast<const int4*>(&g_csrsrc[e]);
                    a += (g_xs[sa.x * DP + fl] + g_xs[sa.y * DP + fl])
                       + (g_xs[sa.z * DP + fl] + g_xs[sa.w * DP + fl]);
                }
                for (; e < e1; e++) a += g_xs[g_csrsrc[e] * DP + fl];
                a = di * (a + g_xs[node * DP + fl]);
            }
        }
        if (fl < DP) sHT[fl][local] = a;
        if (fl == 0) sDI[local] = di;
    }
    __syncthreads();
    int dq = tid & 31, nq = tid >> 5;   // cols (2dq,2dq+1), nodes 4nq..4nq+3
    float acc[4][2];
#pragma unroll
    for (int i = 0; i < 4; i++) { acc[i][0] = sB[2 * dq]; acc[i][1] = sB[2 * dq + 1]; }
#pragma unroll
    for (int k = 0; k < DIN; k++) {
        float4 h4 = *reinterpret_cast<const float4*>(&sHT[k][4 * nq]);
        float2 w2 = *reinterpret_cast<const float2*>(&sW[k * DD + 2 * dq]);
        acc[0][0] += h4.x * w2.x; acc[0][1] += h4.x * w2.y;
        acc[1][0] += h4.y * w2.x; acc[1][1] += h4.y * w2.y;
        acc[2][0] += h4.z * w2.x; acc[2][1] += h4.z * w2.y;
        acc[3][0] += h4.w * w2.x; acc[3][1] += h4.w * w2.y;
    }
#pragma unroll
    for (int i = 0; i < 4; i++) {
        int n = nodeBase + 4 * nq + i;
        if (n < NN) {
            float sc = sDI[4 * nq + i];
            uout[n * 32 + dq] = __floats2half2_rn(sc * tanh_a(acc[i][0]),
                                                  sc * tanh_a(acc[i][1]));
        }
    }
}

// ------------------- fused layer: agg(64, half in) + GEMM64 + tanh (+prescale) -------------------

template <bool OUT_HALF, bool PRESCALE>
__global__ void __launch_bounds__(512) k_layer(const __half2* __restrict__ uin,
                                               const float* __restrict__ W,
                                               const float* __restrict__ bias,
                                               void* __restrict__ uout) {
    __shared__ float sW[DD * DD];   // 16 KB
    __shared__ float sHT[DD][68];   // transposed agg tile
    __shared__ float sB[DD];
    __shared__ float sDI[64];
    int tid = threadIdx.x;
    int nodeBase = blockIdx.x * 64;
    for (int i = tid; i < DD * DD; i += 512) sW[i] = W[i];
    if (tid < DD) sB[tid] = bias[tid];
    int w = tid >> 5, lid = tid & 31;
#pragma unroll
    for (int q = 0; q < 4; q++) {
        int local = w * 4 + q;
        int node = nodeBase + local;
        float ax = 0.f, ay = 0.f, di = 0.f;
        if (node < NN) {
            int e = g_rowptr[node], e1 = g_rowptr[node + 1];
            while (e < e1 && (e & 3)) {
                float2 f = __half22float2(uin[g_csrsrc[e] * 32 + lid]);
                ax += f.x; ay += f.y; e++;
            }
            for (; e + 8 <= e1; e += 8) {
                int4 sa = *reinterpret_cast<const int4*>(&g_csrsrc[e]);
                int4 sb = *reinterpret_cast<const int4*>(&g_csrsrc[e + 4]);
                float2 f0 = __half22float2(uin[sa.x * 32 + lid]);
                float2 f1 = __half22float2(uin[sa.y * 32 + lid]);
                float2 f2 = __half22float2(uin[sa.z * 32 + lid]);
                float2 f3 = __half22float2(uin[sa.w * 32 + lid]);
                float2 f4 = __half22float2(uin[sb.x * 32 + lid]);
                float2 f5 = __half22float2(uin[sb.y * 32 + lid]);
                float2 f6 = __half22float2(uin[sb.z * 32 + lid]);
                float2 f7 = __half22float2(uin[sb.w * 32 + lid]);
                ax += ((f0.x + f1.x) + (f2.x + f3.x)) + ((f4.x + f5.x) + (f6.x + f7.x));
                ay += ((f0.y + f1.y) + (f2.y + f3.y)) + ((f4.y + f5.y) + (f6.y + f7.y));
            }
            for (; e + 4 <= e1; e += 4) {
                int4 sa = *reinterpret_cast<const int4*>(&g_csrsrc[e]);
                float2 f0 = __half22float2(uin[sa.x * 32 + lid]);
                float2 f1 = __half22float2(uin[sa.y * 32 + lid]);
                float2 f2 = __half22float2(uin[sa.z * 32 + lid]);
                float2 f3 = __half22float2(uin[sa.w * 32 + lid]);
                ax += (f0.x + f1.x) + (f2.x + f3.x);
                ay += (f0.y + f1.y) + (f2.y + f3.y);
            }
            for (; e < e1; e++) {
                float2 f = __half22float2(uin[g_csrsrc[e] * 32 + lid]);
                ax += f.x; ay += f.y;
            }
            float2 self = __half22float2(uin[node * 32 + lid]);
            di = g_dinv[node];
            ax = di * (ax + self.x);
            ay = di * (ay + self.y);
        }
        sHT[2 * lid][local] = ax;
        sHT[2 * lid + 1][local] = ay;
        if (lid == 0) sDI[local] = di;
    }
    __syncthreads();
    int dq = tid & 31, nq = tid >> 5;
    float acc[4][2];
#pragma unroll
    for (int i = 0; i < 4; i++) { acc[i][0] = sB[2 * dq]; acc[i][1] = sB[2 * dq + 1]; }
#pragma unroll
    for (int k = 0; k < DD; k++) {
        float4 h4 = *reinterpret_cast<const float4*>(&sHT[k][4 * nq]);
        float2 w2 = *reinterpret_cast<const float2*>(&sW[k * DD + 2 * dq]);
        acc[0][0] += h4.x * w2.x; acc[0][1] += h4.x * w2.y;
        acc[1][0] += h4.y * w2.x; acc[1][1] += h4.y * w2.y;
        acc[2][0] += h4.z * w2.x; acc[2][1] += h4.z * w2.y;
        acc[3][0] += h4.w * w2.x; acc[3][1] += h4.w * w2.y;
    }
#pragma unroll
    for (int i = 0; i < 4; i++) {
        int n = nodeBase + 4 * nq + i;
        if (n < NN) {
            if (OUT_HALF) {
                float sc = PRESCALE ? sDI[4 * nq + i] : 1.0f;
                ((__half2*)uout)[n * 32 + dq] =
                    __floats2half2_rn(sc * tanh_a(acc[i][0]), sc * tanh_a(acc[i][1]));
            } else {
                ((float2*)uout)[n * 32 + dq] =
                    make_float2(tanh_a(acc[i][0]), tanh_a(acc[i][1]));
            }
        }
    }
}

// ------------------- pooling + head -------------------
__global__ void k_pool(const float* __restrict__ h, const float* __restrict__ Wout,
                       const float* __restrict__ bout, float* __restrict__ out) {
    int g = (blockIdx.x * blockDim.x + threadIdx.x) >> 5;
    int lid = threadIdx.x & 31;
    if (g >= GG) return;
    long long gs = (long long)g * NN;
    int start = (int)((gs + GG - 1) / GG);
    int end = (int)((gs + NN + GG - 1) / GG);
    if (end > NN) end = NN;
    const float2* h2 = (const float2*)h;
    float2 mx = make_float2(-INFINITY, -INFINITY);
    float2 sm = make_float2(0.f, 0.f);
    for (int i = start; i < end; i++) {
        float2 v = h2[i * 32 + lid];
        mx.x = fmaxf(mx.x, v.x);
        mx.y = fmaxf(mx.y, v.y);
        sm.x += v.x;
        sm.y += v.y;
    }
    int cnt = end - start; if (cnt < 1) cnt = 1;
    float inv = 1.0f / (float)cnt;
    const float2* w2 = (const float2*)Wout;
    float2 wmx = w2[lid];
    float2 wmn = w2[32 + lid];
    float v = mx.x * wmx.x + mx.y * wmx.y
            + (sm.x * inv) * wmn.x + (sm.y * inv) * wmn.y;
#pragma unroll
    for (int o = 16; o; o >>= 1) v += __shfl_down_sync(0xffffffffu, v, o);
    if (lid == 0) out[g] = v + bout[0];
}

// ------------------- launch -------------------

extern "C" void kernel_launch(void* const* d_in, const int* in_sizes, int n_in,
                              void* d_out, int out_size) {
    const float* x    = (const float*)d_in[0];
    const int*   ei   = (const int*)d_in[1];
    const float* W0   = (const float*)d_in[3];
    const float* b0   = (const float*)d_in[4];
    const float* W1   = (const float*)d_in[5];
    const float* b1   = (const float*)d_in[6];
    const float* W2   = (const float*)d_in[7];
    const float* b2   = (const float*)d_in[8];
    const float* W3   = (const float*)d_in[9];
    const float* b3   = (const float*)d_in[10];
    const float* Wout = (const float*)d_in[11];
    const float* bout = (const float*)d_in[12];
    float* out = (float*)d_out;

    const int* erow = ei;        // sources
    const int* ecol = ei + EE;   // destinations

    float *hA, *hB;
    cudaGetSymbolAddress((void**)&hA, g_hA);
    cudaGetSymbolAddress((void**)&hB, g_hB);

    int eB4 = (EE / 4 + 255) / 256;   // 782: 4 edges/thread
    int gB = (NN + 63) / 64;          // 782 layer blocks
    int pB = (GG * 32 + 255) / 256;

    k_hist<<<eB4, 256>>>(ecol);
    k_scan<<<NBLK, 256>>>(x);
    k_fill<<<eB4, 256>>>(erow, ecol);

    k_layer0<<<gB, 512>>>(W0, b0, (__half2*)hA);
    k_layer<true, true><<<gB, 512>>>((const __half2*)hA, W1, b1, hB);
    k_layer<true, true><<<gB, 512>>>((const __half2*)hB, W2, b2, hA);
    k_layer<false, false><<<gB, 512>>>((const __half2*)hA, W3, b3, hB);

    k_pool<<<pB, 256>>>(hB, Wout, bout, out);
}

// round 9
// speedup vs baseline: 2.1203x; 1.0237x over previous
#include <cuda_runtime.h>
#include <cuda_fp16.h>
#include <math.h>

#define NN 50000
#define EE 800000
#define GG 1024
#define DD 64
#define DIN 9
#define DP 12
#define NBLK ((NN + 255) / 256)   // 196

// ---- scratch ----
__device__ int   g_deg[NN];        // all-zero at entry; re-zeroed in k_fill each call
__device__ float g_dinv[NN];
__device__ int   g_rowptr[NN + 1];
__device__ int   g_cursor[NN];
__device__ int   g_csrsrc[EE];
__device__ unsigned long long g_blkDesc[NBLK];  // zeroed in k_hist each call
__device__ float g_xs[NN * DP];
__device__ float g_hA[NN * DD];
__device__ float g_hB[NN * DD];

__device__ __forceinline__ float tanh_a(float x) {
    float y;
    asm("tanh.approx.f32 %0, %1;" : "=f"(y) : "f"(x));
    return y;
}

__device__ __forceinline__ unsigned long long pack2(float lo, float hi) {
    unsigned long long r;
    asm("mov.b64 %0, {%1, %2};" : "=l"(r) : "r"(__float_as_uint(lo)), "r"(__float_as_uint(hi)));
    return r;
}
__device__ __forceinline__ void unpack2(unsigned long long v, float& lo, float& hi) {
    unsigned int a, b;
    asm("mov.b64 {%0, %1}, %2;" : "=r"(a), "=r"(b) : "l"(v));
    lo = __uint_as_float(a); hi = __uint_as_float(b);
}
__device__ __forceinline__ void fma2(unsigned long long& acc, unsigned long long a,
                                     unsigned long long b) {
    asm("fma.rn.f32x2 %0, %1, %2, %0;" : "+l"(acc) : "l"(a), "l"(b));
}

// ------------------- preprocessing -------------------

__global__ void k_hist(const int* __restrict__ col) {
    int i = blockIdx.x * blockDim.x + threadIdx.x;
    if (i < NBLK) g_blkDesc[i] = 0ULL;
    if (i * 4 < EE) {
        int4 c = reinterpret_cast<const int4*>(col)[i];
        atomicAdd(&g_deg[c.x], 1);
        atomicAdd(&g_deg[c.y], 1);
        atomicAdd(&g_deg[c.z], 1);
        atomicAdd(&g_deg[c.w], 1);
    }
}

__global__ void k_scan(const float* __restrict__ x) {
    __shared__ int wsum[8];
    __shared__ int sprefix;
    int b = blockIdx.x, t = threadIdx.x;
    int i = b * 256 + t;
    int lane = t & 31, w = t >> 5;
    int v = (i < NN) ? g_deg[i] : 0;
    int s = v;
#pragma unroll
    for (int o = 1; o < 32; o <<= 1) {
        int u = __shfl_up_sync(~0u, s, o);
        if (lane >= o) s += u;
    }
    if (lane == 31) wsum[w] = s;
    __syncthreads();
    if (w == 0) {
        int ws = (lane < 8) ? wsum[lane] : 0;
#pragma unroll
        for (int o = 1; o < 8; o <<= 1) {
            int u = __shfl_up_sync(0xffu, ws, o);
            if (lane >= o) ws += u;
        }
        if (lane < 8) wsum[lane] = ws;
    }
    __syncthreads();
    int total = wsum[7];
    if (t == 0) {
        if (b == 0) {
            atomicExch(&g_blkDesc[0], ((unsigned long long)total << 2) | 2ULL);
            sprefix = 0;
        } else {
            atomicExch(&g_blkDesc[b], ((unsigned long long)total << 2) | 1ULL);
            int run = 0;
            for (int j = b - 1; j >= 0; j--) {
                unsigned long long d;
                do { d = *((volatile unsigned long long*)&g_blkDesc[j]); } while ((d & 3ULL) == 0ULL);
                run += (int)(d >> 2);
                if ((d & 3ULL) == 2ULL) break;
            }
            sprefix = run;
            atomicExch(&g_blkDesc[b], ((unsigned long long)(total + run) << 2) | 2ULL);
        }
    }
    __syncthreads();
    int excl = sprefix + (w > 0 ? wsum[w - 1] : 0) + (s - v);
    if (i < NN) {
        g_rowptr[i] = excl;
        g_cursor[i] = excl;
        float di = rsqrtf((float)v + 1.0f);  // +1 self loop
        g_dinv[i] = di;
#pragma unroll
        for (int c = 0; c < DIN; c++) g_xs[i * DP + c] = di * x[i * DIN + c];
#pragma unroll
        for (int c = DIN; c < DP; c++) g_xs[i * DP + c] = 0.f;
    }
    if (i == 0) g_rowptr[NN] = EE;
}

__global__ void k_fill(const int* __restrict__ row, const int* __restrict__ col) {
    int i = blockIdx.x * blockDim.x + threadIdx.x;
    if (i < NN) g_deg[i] = 0;
    if (i * 4 < EE) {
        int4 r = reinterpret_cast<const int4*>(row)[i];
        int4 c = reinterpret_cast<const int4*>(col)[i];
        g_csrsrc[atomicAdd(&g_cursor[c.x], 1)] = r.x;
        g_csrsrc[atomicAdd(&g_cursor[c.y], 1)] = r.y;
        g_csrsrc[atomicAdd(&g_cursor[c.z], 1)] = r.z;
        g_csrsrc[atomicAdd(&g_cursor[c.w], 1)] = r.w;
    }
}

// ------------------- fused layer 0 (unchanged from R8) -------------------

__global__ void __launch_bounds__(512) k_layer0(const float* __restrict__ W0,
                                                const float* __restrict__ b0,
                                                __half2* __restrict__ uout) {
    __shared__ float sW[DIN * DD];
    __shared__ float sHT[DP][68];
    __shared__ float sB[DD];
    __shared__ float sDI[64];
    int tid = threadIdx.x;
    int nodeBase = blockIdx.x * 64;
    for (int i = tid; i < DIN * DD; i += 512) sW[i] = W0[i];
    if (tid < DD) sB[tid] = b0[tid];
    int w = tid >> 5, lid = tid & 31;
    int sub = lid >> 4;
    int fl = lid & 15;
#pragma unroll
    for (int pass = 0; pass < 2; pass++) {
        int local = w * 4 + pass * 2 + sub;
        int node = nodeBase + local;
        float a = 0.f, di = 0.f;
        if (node < NN) {
            di = g_dinv[node];
            if (fl < DP) {
                int e = g_rowptr[node], e1 = g_rowptr[node + 1];
                while (e < e1 && (e & 3)) { a += g_xs[g_csrsrc[e] * DP + fl]; e++; }
                for (; e + 8 <= e1; e += 8) {
                    int4 sa = *reinterpret_cast<const int4*>(&g_csrsrc[e]);
                    int4 sb = *reinterpret_cast<const int4*>(&g_csrsrc[e + 4]);
                    a += (g_xs[sa.x * DP + fl] + g_xs[sa.y * DP + fl])
                       + (g_xs[sa.z * DP + fl] + g_xs[sa.w * DP + fl])
                       + (g_xs[sb.x * DP + fl] + g_xs[sb.y * DP + fl])
                       + (g_xs[sb.z * DP + fl] + g_xs[sb.w * DP + fl]);
                }
                for (; e + 4 <= e1; e += 4) {
                    int4 sa = *reinterpret_cast<const int4*>(&g_csrsrc[e]);
                    a += (g_xs[sa.x * DP + fl] + g_xs[sa.y * DP + fl])
                       + (g_xs[sa.z * DP + fl] + g_xs[sa.w * DP + fl]);
                }
                for (; e < e1; e++) a += g_xs[g_csrsrc[e] * DP + fl];
                a = di * (a + g_xs[node * DP + fl]);
            }
        }
        if (fl < DP) sHT[fl][local] = a;
        if (fl == 0) sDI[local] = di;
    }
    __syncthreads();
    int dq = tid & 31, nq = tid >> 5;
    float acc[4][2];
#pragma unroll
    for (int i = 0; i < 4; i++) { acc[i][0] = sB[2 * dq]; acc[i][1] = sB[2 * dq + 1]; }
#pragma unroll
    for (int k = 0; k < DIN; k++) {
        float4 h4 = *reinterpret_cast<const float4*>(&sHT[k][4 * nq]);
        float2 w2 = *reinterpret_cast<const float2*>(&sW[k * DD + 2 * dq]);
        acc[0][0] += h4.x * w2.x; acc[0][1] += h4.x * w2.y;
        acc[1][0] += h4.y * w2.x; acc[1][1] += h4.y * w2.y;
        acc[2][0] += h4.z * w2.x; acc[2][1] += h4.z * w2.y;
        acc[3][0] += h4.w * w2.x; acc[3][1] += h4.w * w2.y;
    }
#pragma unroll
    for (int i = 0; i < 4; i++) {
        int n = nodeBase + 4 * nq + i;
        if (n < NN) {
            float sc = sDI[4 * nq + i];
            uout[n * 32 + dq] = __floats2half2_rn(sc * tanh_a(acc[i][0]),
                                                  sc * tanh_a(acc[i][1]));
        }
    }
}

// ------------------- fused layer: half-warp gather + f32x2 GEMM -------------------

template <bool OUT_HALF, bool PRESCALE>
__global__ void __launch_bounds__(512, 2) k_layer(const __half2* __restrict__ uin,
                                                  const float* __restrict__ W,
                                                  const float* __restrict__ bias,
                                                  void* __restrict__ uout) {
    __shared__ float sW[DD * DD];   // 16 KB
    __shared__ float sHT[DD][68];   // transposed agg tile
    __shared__ float sB[DD];
    __shared__ float sDI[64];
    int tid = threadIdx.x;
    int nodeBase = blockIdx.x * 64;
    for (int i = tid; i < DD * DD; i += 512) sW[i] = W[i];
    if (tid < DD) sB[tid] = bias[tid];
    int w = tid >> 5, lid = tid & 31;
    int hw = lid >> 4;          // which node of the pair
    int cl = lid & 15;          // column quad: cols 4cl..4cl+3
    const uint2* u2 = (const uint2*)uin;
#pragma unroll
    for (int pass = 0; pass < 2; pass++) {
        int local = w * 4 + pass * 2 + hw;
        int node = nodeBase + local;
        float a0 = 0.f, a1 = 0.f, a2 = 0.f, a3 = 0.f, di = 0.f;
        if (node < NN) {
            int e = g_rowptr[node], e1 = g_rowptr[node + 1];
            for (; e + 4 <= e1; e += 4) {
                int s0 = g_csrsrc[e + 0];
                int s1 = g_csrsrc[e + 1];
                int s2 = g_csrsrc[e + 2];
                int s3 = g_csrsrc[e + 3];
                uint2 q0 = u2[s0 * 16 + cl];
                uint2 q1 = u2[s1 * 16 + cl];
                uint2 q2 = u2[s2 * 16 + cl];
                uint2 q3 = u2[s3 * 16 + cl];
                float2 f;
                f = __half22float2(*(const __half2*)&q0.x); a0 += f.x; a1 += f.y;
                f = __half22float2(*(const __half2*)&q0.y); a2 += f.x; a3 += f.y;
                f = __half22float2(*(const __half2*)&q1.x); a0 += f.x; a1 += f.y;
                f = __half22float2(*(const __half2*)&q1.y); a2 += f.x; a3 += f.y;
                f = __half22float2(*(const __half2*)&q2.x); a0 += f.x; a1 += f.y;
                f = __half22float2(*(const __half2*)&q2.y); a2 += f.x; a3 += f.y;
                f = __half22float2(*(const __half2*)&q3.x); a0 += f.x; a1 += f.y;
                f = __half22float2(*(const __half2*)&q3.y); a2 += f.x; a3 += f.y;
            }
            for (; e < e1; e++) {
                uint2 q = u2[g_csrsrc[e] * 16 + cl];
                float2 f;
                f = __half22float2(*(const __half2*)&q.x); a0 += f.x; a1 += f.y;
                f = __half22float2(*(const __half2*)&q.y); a2 += f.x; a3 += f.y;
            }
            uint2 qs = u2[node * 16 + cl];
            float2 s0 = __half22float2(*(const __half2*)&qs.x);
            float2 s1 = __half22float2(*(const __half2*)&qs.y);
            di = g_dinv[node];
            a0 = di * (a0 + s0.x);
            a1 = di * (a1 + s0.y);
            a2 = di * (a2 + s1.x);
            a3 = di * (a3 + s1.y);
        }
        sHT[4 * cl + 0][local] = a0;
        sHT[4 * cl + 1][local] = a1;
        sHT[4 * cl + 2][local] = a2;
        sHT[4 * cl + 3][local] = a3;
        if (cl == 0) sDI[local] = di;
    }
    __syncthreads();
    // GEMM: thread handles cols (2dq, 2dq+1) x nodes 4nq..4nq+3, packed over node pairs
    int dq = tid & 31, nq = tid >> 5;
    float bx = sB[2 * dq], by = sB[2 * dq + 1];
    unsigned long long accX01 = pack2(bx, bx);   // col 2dq,   nodes 0,1
    unsigned long long accX23 = pack2(bx, bx);   // col 2dq,   nodes 2,3
    unsigned long long accY01 = pack2(by, by);   // col 2dq+1, nodes 0,1
    unsigned long long accY23 = pack2(by, by);   // col 2dq+1, nodes 2,3
#pragma unroll
    for (int k = 0; k < DD; k++) {
        unsigned long long h01 = *reinterpret_cast<const unsigned long long*>(&sHT[k][4 * nq]);
        unsigned long long h23 = *reinterpret_cast<const unsigned long long*>(&sHT[k][4 * nq + 2]);
        float2 wv = *reinterpret_cast<const float2*>(&sW[k * DD + 2 * dq]);
        unsigned long long wx2 = pack2(wv.x, wv.x);
        unsigned long long wy2 = pack2(wv.y, wv.y);
        fma2(accX01, h01, wx2);
        fma2(accX23, h23, wx2);
        fma2(accY01, h01, wy2);
        fma2(accY23, h23, wy2);
    }
    float x0, x1, x2, x3, y0, y1, y2, y3;
    unpack2(accX01, x0, x1); unpack2(accX23, x2, x3);
    unpack2(accY01, y0, y1); unpack2(accY23, y2, y3);
    float cx[4] = {x0, x1, x2, x3};
    float cy[4] = {y0, y1, y2, y3};
#pragma unroll
    for (int i = 0; i < 4; i++) {
        int n = nodeBase + 4 * nq + i;
        if (n < NN) {
            if (OUT_HALF) {
                float sc = PRESCALE ? sDI[4 * nq + i] : 1.0f;
                ((__half2*)uout)[n * 32 + dq] =
                    __floats2half2_rn(sc * tanh_a(cx[i]), sc * tanh_a(cy[i]));
            } else {
                ((float2*)uout)[n * 32 + dq] =
                    make_float2(tanh_a(cx[i]), tanh_a(cy[i]));
            }
        }
    }
}

// ------------------- pooling + head -------------------
__global__ void k_pool(const float* __restrict__ h, const float* __restrict__ Wout,
                       const float* __restrict__ bout, float* __restrict__ out) {
    int g = (blockIdx.x * blockDim.x + threadIdx.x) >> 5;
    int lid = threadIdx.x & 31;
    if (g >= GG) return;
    long long gs = (long long)g * NN;
    int start = (int)((gs + GG - 1) / GG);
    int end = (int)((gs + NN + GG - 1) / GG);
    if (end > NN) end = NN;
    const float2* h2 = (const float2*)h;
    float2 mx = make_float2(-INFINITY, -INFINITY);
    float2 sm = make_float2(0.f, 0.f);
    for (int i = start; i < end; i++) {
        float2 v = h2[i * 32 + lid];
        mx.x = fmaxf(mx.x, v.x);
        mx.y = fmaxf(mx.y, v.y);
        sm.x += v.x;
        sm.y += v.y;
    }
    int cnt = end - start; if (cnt < 1) cnt = 1;
    float inv = 1.0f / (float)cnt;
    const float2* w2 = (const float2*)Wout;
    float2 wmx = w2[lid];
    float2 wmn = w2[32 + lid];
    float v = mx.x * wmx.x + mx.y * wmx.y
            + (sm.x * inv) * wmn.x + (sm.y * inv) * wmn.y;
#pragma unroll
    for (int o = 16; o; o >>= 1) v += __shfl_down_sync(0xffffffffu, v, o);
    if (lid == 0) out[g] = v + bout[0];
}

// ------------------- launch -------------------

extern "C" void kernel_launch(void* const* d_in, const int* in_sizes, int n_in,
                              void* d_out, int out_size) {
    const float* x    = (const float*)d_in[0];
    const int*   ei   = (const int*)d_in[1];
    const float* W0   = (const float*)d_in[3];
    const float* b0   = (const float*)d_in[4];
    const float* W1   = (const float*)d_in[5];
    const float* b1   = (const float*)d_in[6];
    const float* W2   = (const float*)d_in[7];
    const float* b2   = (const float*)d_in[8];
    const float* W3   = (const float*)d_in[9];
    const float* b3   = (const float*)d_in[10];
    const float* Wout = (const float*)d_in[11];
    const float* bout = (const float*)d_in[12];
    float* out = (float*)d_out;

    const int* erow = ei;        // sources
    const int* ecol = ei + EE;   // destinations

    float *hA, *hB;
    cudaGetSymbolAddress((void**)&hA, g_hA);
    cudaGetSymbolAddress((void**)&hB, g_hB);

    int eB4 = (EE / 4 + 255) / 256;   // 782
    int gB = (NN + 63) / 64;          // 782
    int pB = (GG * 32 + 255) / 256;

    k_hist<<<eB4, 256>>>(ecol);
    k_scan<<<NBLK, 256>>>(x);
    k_fill<<<eB4, 256>>>(erow, ecol);

    k_layer0<<<gB, 512>>>(W0, b0, (__half2*)hA);
    k_layer<true, true><<<gB, 512>>>((const __half2*)hA, W1, b1, hB);
    k_layer<true, true><<<gB, 512>>>((const __half2*)hB, W2, b2, hA);
    k_layer<false, false><<<gB, 512>>>((const __half2*)hA, W3, b3, hB);

    k_pool<<<pB, 256>>>(hB, Wout, bout, out);
}

// round 10
// speedup vs baseline: 2.2309x; 1.0521x over previous
#include <cuda_runtime.h>
#include <cuda_fp16.h>
#include <math.h>

#define NN 50000
#define EE 800000
#define GG 1024
#define DD 64
#define DIN 9
#define DP 16                      // padded input dim (4 x float4)
#define NBLK ((NN + 255) / 256)    // 196

// ---- scratch ----
__device__ int   g_deg[NN];        // all-zero at entry; re-zeroed in k_fill each call
__device__ float g_dinv[NN];
__device__ int   g_rowptr[NN + 1];
__device__ int   g_cursor[NN];
__device__ int   g_csrsrc[EE];
__device__ unsigned long long g_blkDesc[NBLK];  // zeroed in k_hist each call
__device__ float g_xs[NN * DP];
__device__ float g_hA[NN * DD];
__device__ float g_hB[NN * DD];

__device__ __forceinline__ float tanh_a(float x) {
    float y;
    asm("tanh.approx.f32 %0, %1;" : "=f"(y) : "f"(x));
    return y;
}
__device__ __forceinline__ unsigned long long pack2(float lo, float hi) {
    unsigned long long r;
    asm("mov.b64 %0, {%1, %2};" : "=l"(r) : "r"(__float_as_uint(lo)), "r"(__float_as_uint(hi)));
    return r;
}
__device__ __forceinline__ void unpack2(unsigned long long v, float& lo, float& hi) {
    unsigned int a, b;
    asm("mov.b64 {%0, %1}, %2;" : "=r"(a), "=r"(b) : "l"(v));
    lo = __uint_as_float(a); hi = __uint_as_float(b);
}
__device__ __forceinline__ void fma2(unsigned long long& acc, unsigned long long a,
                                     unsigned long long b) {
    asm("fma.rn.f32x2 %0, %1, %2, %0;" : "+l"(acc) : "l"(a), "l"(b));
}
__device__ __forceinline__ int sel4(int4 v, int g) {
    return g == 0 ? v.x : (g == 1 ? v.y : (g == 2 ? v.z : v.w));
}

// ------------------- preprocessing -------------------

__global__ void k_hist(const int* __restrict__ col) {
    int i = blockIdx.x * blockDim.x + threadIdx.x;
    if (i < NBLK) g_blkDesc[i] = 0ULL;
    long long base = (long long)i * 8;
    if (base < EE) {
        int4 a = reinterpret_cast<const int4*>(col)[i * 2];
        int4 b = reinterpret_cast<const int4*>(col)[i * 2 + 1];
        atomicAdd(&g_deg[a.x], 1); atomicAdd(&g_deg[a.y], 1);
        atomicAdd(&g_deg[a.z], 1); atomicAdd(&g_deg[a.w], 1);
        atomicAdd(&g_deg[b.x], 1); atomicAdd(&g_deg[b.y], 1);
        atomicAdd(&g_deg[b.z], 1); atomicAdd(&g_deg[b.w], 1);
    }
}

__global__ void k_scan(const float* __restrict__ x) {
    __shared__ int wsum[8];
    __shared__ int sprefix;
    int b = blockIdx.x, t = threadIdx.x;
    int i = b * 256 + t;
    int lane = t & 31, w = t >> 5;
    int v = (i < NN) ? g_deg[i] : 0;
    int s = v;
#pragma unroll
    for (int o = 1; o < 32; o <<= 1) {
        int u = __shfl_up_sync(~0u, s, o);
        if (lane >= o) s += u;
    }
    if (lane == 31) wsum[w] = s;
    __syncthreads();
    if (w == 0) {
        int ws = (lane < 8) ? wsum[lane] : 0;
#pragma unroll
        for (int o = 1; o < 8; o <<= 1) {
            int u = __shfl_up_sync(0xffu, ws, o);
            if (lane >= o) ws += u;
        }
        if (lane < 8) wsum[lane] = ws;
    }
    __syncthreads();
    int total = wsum[7];
    if (t == 0) {
        if (b == 0) {
            atomicExch(&g_blkDesc[0], ((unsigned long long)total << 2) | 2ULL);
            sprefix = 0;
        } else {
            atomicExch(&g_blkDesc[b], ((unsigned long long)total << 2) | 1ULL);
            int run = 0;
            for (int j = b - 1; j >= 0; j--) {
                unsigned long long d;
                do { d = *((volatile unsigned long long*)&g_blkDesc[j]); } while ((d & 3ULL) == 0ULL);
                run += (int)(d >> 2);
                if ((d & 3ULL) == 2ULL) break;
            }
            sprefix = run;
            atomicExch(&g_blkDesc[b], ((unsigned long long)(total + run) << 2) | 2ULL);
        }
    }
    __syncthreads();
    int excl = sprefix + (w > 0 ? wsum[w - 1] : 0) + (s - v);
    if (i < NN) {
        g_rowptr[i] = excl;
        g_cursor[i] = excl;
        float di = rsqrtf((float)v + 1.0f);  // +1 self loop
        g_dinv[i] = di;
#pragma unroll
        for (int c = 0; c < DIN; c++) g_xs[i * DP + c] = di * x[i * DIN + c];
#pragma unroll
        for (int c = DIN; c < DP; c++) g_xs[i * DP + c] = 0.f;
    }
    if (i == 0) g_rowptr[NN] = EE;
}

__global__ void k_fill(const int* __restrict__ row, const int* __restrict__ col) {
    int i = blockIdx.x * blockDim.x + threadIdx.x;
    if (i < NN) g_deg[i] = 0;
    long long base = (long long)i * 8;
    if (base < EE) {
        int4 ra = reinterpret_cast<const int4*>(row)[i * 2];
        int4 rb = reinterpret_cast<const int4*>(row)[i * 2 + 1];
        int4 ca = reinterpret_cast<const int4*>(col)[i * 2];
        int4 cb = reinterpret_cast<const int4*>(col)[i * 2 + 1];
        g_csrsrc[atomicAdd(&g_cursor[ca.x], 1)] = ra.x;
        g_csrsrc[atomicAdd(&g_cursor[ca.y], 1)] = ra.y;
        g_csrsrc[atomicAdd(&g_cursor[ca.z], 1)] = ra.z;
        g_csrsrc[atomicAdd(&g_cursor[ca.w], 1)] = ra.w;
        g_csrsrc[atomicAdd(&g_cursor[cb.x], 1)] = rb.x;
        g_csrsrc[atomicAdd(&g_cursor[cb.y], 1)] = rb.y;
        g_csrsrc[atomicAdd(&g_cursor[cb.z], 1)] = rb.z;
        g_csrsrc[atomicAdd(&g_cursor[cb.w], 1)] = rb.w;
    }
}

// ------------------- fused layer 0: wide-lane gather (4 nbrs/instr) + GEMM0 -------------------

__global__ void __launch_bounds__(512) k_layer0(const float* __restrict__ W0,
                                                const float* __restrict__ b0,
                                                __half2* __restrict__ uout) {
    __shared__ float sW[DIN * DD];
    __shared__ float sHT[DP][68];   // [feature][node]
    __shared__ float sB[DD];
    __shared__ float sDI[64];
    int tid = threadIdx.x;
    int nodeBase = blockIdx.x * 64;
    for (int i = tid; i < DIN * DD; i += 512) sW[i] = W0[i];
    if (tid < DD) sB[tid] = b0[tid];
    int w = tid >> 5, lid = tid & 31;
    int hw = lid >> 4;       // node of pair
    int sl = lid & 15;
    int g4 = sl >> 2;        // neighbor slot (0..3)
    int c4 = sl & 3;         // float4 column (feats 4c4..4c4+3)
    const float4* xs4 = (const float4*)g_xs;
#pragma unroll
    for (int pass = 0; pass < 2; pass++) {
        int local = w * 4 + pass * 2 + hw;
        int node = nodeBase + local;
        float4 a = make_float4(0.f, 0.f, 0.f, 0.f);
        float di = 0.f;
        if (node < NN) {
            di = g_dinv[node];
            int e = g_rowptr[node], e1 = g_rowptr[node + 1];
            int mis = (4 - (e & 3)) & 3;
            int rem = e1 - e; if (mis > rem) mis = rem;
            if (mis & 1) {
                if (g4 == 0) { float4 q = xs4[g_csrsrc[e] * 4 + c4]; a.x += q.x; a.y += q.y; a.z += q.z; a.w += q.w; }
                e += 1;
            }
            if (mis & 2) {
                if (g4 < 2) { float4 q = xs4[g_csrsrc[e + g4] * 4 + c4]; a.x += q.x; a.y += q.y; a.z += q.z; a.w += q.w; }
                e += 2;
            }
            for (; e + 16 <= e1; e += 16) {
                int4 i0 = *reinterpret_cast<const int4*>(&g_csrsrc[e]);
                int4 i1 = *reinterpret_cast<const int4*>(&g_csrsrc[e + 4]);
                int4 i2 = *reinterpret_cast<const int4*>(&g_csrsrc[e + 8]);
                int4 i3 = *reinterpret_cast<const int4*>(&g_csrsrc[e + 12]);
                float4 q0 = xs4[sel4(i0, g4) * 4 + c4];
                float4 q1 = xs4[sel4(i1, g4) * 4 + c4];
                float4 q2 = xs4[sel4(i2, g4) * 4 + c4];
                float4 q3 = xs4[sel4(i3, g4) * 4 + c4];
                a.x += (q0.x + q1.x) + (q2.x + q3.x);
                a.y += (q0.y + q1.y) + (q2.y + q3.y);
                a.z += (q0.z + q1.z) + (q2.z + q3.z);
                a.w += (q0.w + q1.w) + (q2.w + q3.w);
            }
            for (; e + 4 <= e1; e += 4) {
                int4 i0 = *reinterpret_cast<const int4*>(&g_csrsrc[e]);
                float4 q = xs4[sel4(i0, g4) * 4 + c4];
                a.x += q.x; a.y += q.y; a.z += q.z; a.w += q.w;
            }
            if (e + 2 <= e1) {
                if (g4 < 2) { float4 q = xs4[g_csrsrc[e + g4] * 4 + c4]; a.x += q.x; a.y += q.y; a.z += q.z; a.w += q.w; }
                e += 2;
            }
            if (e < e1 && g4 == 0) {
                float4 q = xs4[g_csrsrc[e] * 4 + c4];
                a.x += q.x; a.y += q.y; a.z += q.z; a.w += q.w;
            }
        }
        // merge the 4 neighbor-slot groups (within 16-lane segment)
#pragma unroll
        for (int o = 8; o >= 4; o >>= 1) {
            a.x += __shfl_down_sync(~0u, a.x, o, 16);
            a.y += __shfl_down_sync(~0u, a.y, o, 16);
            a.z += __shfl_down_sync(~0u, a.z, o, 16);
            a.w += __shfl_down_sync(~0u, a.w, o, 16);
        }
        if (sl < 4) {
            if (node < NN) {
                float4 s = xs4[node * 4 + sl];
                a.x = di * (a.x + s.x); a.y = di * (a.y + s.y);
                a.z = di * (a.z + s.z); a.w = di * (a.w + s.w);
            } else { a = make_float4(0.f, 0.f, 0.f, 0.f); }
            sHT[4 * sl + 0][local] = a.x;
            sHT[4 * sl + 1][local] = a.y;
            sHT[4 * sl + 2][local] = a.z;
            sHT[4 * sl + 3][local] = a.w;
            if (sl == 0) sDI[local] = di;
        }
    }
    __syncthreads();
    int dq = tid & 31, nq = tid >> 5;
    float acc[4][2];
#pragma unroll
    for (int i = 0; i < 4; i++) { acc[i][0] = sB[2 * dq]; acc[i][1] = sB[2 * dq + 1]; }
#pragma unroll
    for (int k = 0; k < DIN; k++) {
        float4 h4 = *reinterpret_cast<const float4*>(&sHT[k][4 * nq]);
        float2 w2 = *reinterpret_cast<const float2*>(&sW[k * DD + 2 * dq]);
        acc[0][0] += h4.x * w2.x; acc[0][1] += h4.x * w2.y;
        acc[1][0] += h4.y * w2.x; acc[1][1] += h4.y * w2.y;
        acc[2][0] += h4.z * w2.x; acc[2][1] += h4.z * w2.y;
        acc[3][0] += h4.w * w2.x; acc[3][1] += h4.w * w2.y;
    }
#pragma unroll
    for (int i = 0; i < 4; i++) {
        int n = nodeBase + 4 * nq + i;
        if (n < NN) {
            float sc = sDI[4 * nq + i];
            uout[n * 32 + dq] = __floats2half2_rn(sc * tanh_a(acc[i][0]),
                                                  sc * tanh_a(acc[i][1]));
        }
    }
}

// ------------------- fused layer: wide-lane gather (2 nbrs/instr) + f32x2 GEMM -------------------

#define ACC8(q)                                                              \
    { float2 f;                                                              \
      f = __half22float2(*(const __half2*)&(q).x); a0 += f.x; a1 += f.y;     \
      f = __half22float2(*(const __half2*)&(q).y); a2 += f.x; a3 += f.y;     \
      f = __half22float2(*(const __half2*)&(q).z); a4 += f.x; a5 += f.y;     \
      f = __half22float2(*(const __half2*)&(q).w); a6 += f.x; a7 += f.y; }

template <bool OUT_HALF, bool PRESCALE>
__global__ void __launch_bounds__(512) k_layer(const __half2* __restrict__ uin,
                                               const float* __restrict__ W,
                                               const float* __restrict__ bias,
                                               void* __restrict__ uout) {
    __shared__ float sW[DD * DD];   // 16 KB
    __shared__ float sHT[DD][68];   // [col][node], node column swizzled by (c8<<2)
    __shared__ float sB[DD];
    __shared__ float sDI[64];
    int tid = threadIdx.x;
    int nodeBase = blockIdx.x * 64;
    for (int i = tid; i < DD * DD; i += 512) sW[i] = W[i];
    if (tid < DD) sB[tid] = bias[tid];
    int w = tid >> 5, lid = tid & 31;
    int hw = lid >> 4;      // node of pair
    int sl = lid & 15;
    int g8 = sl >> 3;       // neighbor slot (0/1)
    int c8 = sl & 7;        // uint4 col (half-cols 8c8..8c8+7)
    const uint4* u4 = (const uint4*)uin;
#pragma unroll
    for (int pass = 0; pass < 2; pass++) {
        int local = w * 4 + pass * 2 + hw;
        int node = nodeBase + local;
        float a0 = 0.f, a1 = 0.f, a2 = 0.f, a3 = 0.f;
        float a4 = 0.f, a5 = 0.f, a6 = 0.f, a7 = 0.f;
        float di = 0.f;
        if (node < NN) {
            di = g_dinv[node];
            int e = g_rowptr[node], e1 = g_rowptr[node + 1];
            int mis = (4 - (e & 3)) & 3;
            int rem = e1 - e; if (mis > rem) mis = rem;
            if (mis & 1) {
                if (g8 == 0) { uint4 q = u4[g_csrsrc[e] * 8 + c8]; ACC8(q); }
                e += 1;
            }
            if (mis & 2) {
                uint4 q = u4[g_csrsrc[e + g8] * 8 + c8]; ACC8(q);
                e += 2;
            }
            for (; e + 8 <= e1; e += 8) {
                int4 iA = *reinterpret_cast<const int4*>(&g_csrsrc[e]);
                int4 iB = *reinterpret_cast<const int4*>(&g_csrsrc[e + 4]);
                uint4 q0 = u4[(g8 ? iA.y : iA.x) * 8 + c8];
                uint4 q1 = u4[(g8 ? iA.w : iA.z) * 8 + c8];
                uint4 q2 = u4[(g8 ? iB.y : iB.x) * 8 + c8];
                uint4 q3 = u4[(g8 ? iB.w : iB.z) * 8 + c8];
                ACC8(q0); ACC8(q1); ACC8(q2); ACC8(q3);
            }
            if (e + 4 <= e1) {
                int4 iA = *reinterpret_cast<const int4*>(&g_csrsrc[e]);
                uint4 q0 = u4[(g8 ? iA.y : iA.x) * 8 + c8];
                uint4 q1 = u4[(g8 ? iA.w : iA.z) * 8 + c8];
                ACC8(q0); ACC8(q1);
                e += 4;
            }
            if (e + 2 <= e1) {
                uint4 q = u4[g_csrsrc[e + g8] * 8 + c8]; ACC8(q);
                e += 2;
            }
            if (e < e1 && g8 == 0) {
                uint4 q = u4[g_csrsrc[e] * 8 + c8]; ACC8(q);
            }
        }
        // merge the two neighbor-slot groups (within 16-lane segment)
        a0 += __shfl_down_sync(~0u, a0, 8, 16);
        a1 += __shfl_down_sync(~0u, a1, 8, 16);
        a2 += __shfl_down_sync(~0u, a2, 8, 16);
        a3 += __shfl_down_sync(~0u, a3, 8, 16);
        a4 += __shfl_down_sync(~0u, a4, 8, 16);
        a5 += __shfl_down_sync(~0u, a5, 8, 16);
        a6 += __shfl_down_sync(~0u, a6, 8, 16);
        a7 += __shfl_down_sync(~0u, a7, 8, 16);
        if (sl < 8) {
            if (node < NN) {
                uint4 qs = u4[node * 8 + c8];
                float2 f;
                f = __half22float2(*(const __half2*)&qs.x); a0 = di * (a0 + f.x); a1 = di * (a1 + f.y);
                f = __half22float2(*(const __half2*)&qs.y); a2 = di * (a2 + f.x); a3 = di * (a3 + f.y);
                f = __half22float2(*(const __half2*)&qs.z); a4 = di * (a4 + f.x); a5 = di * (a5 + f.y);
                f = __half22float2(*(const __half2*)&qs.w); a6 = di * (a6 + f.x); a7 = di * (a7 + f.y);
            } else {
                a0 = a1 = a2 = a3 = a4 = a5 = a6 = a7 = 0.f;
            }
            int col = local ^ (c8 << 2);   // bank-conflict-free swizzle
            sHT[8 * c8 + 0][col] = a0;
            sHT[8 * c8 + 1][col] = a1;
            sHT[8 * c8 + 2][col] = a2;
            sHT[8 * c8 + 3][col] = a3;
            sHT[8 * c8 + 4][col] = a4;
            sHT[8 * c8 + 5][col] = a5;
            sHT[8 * c8 + 6][col] = a6;
            sHT[8 * c8 + 7][col] = a7;
            if (c8 == 0) sDI[local] = di;
        }
    }
    __syncthreads();
    // GEMM: cols (2dq, 2dq+1) x nodes 4nq..4nq+3, f32x2-packed over node pairs
    int dq = tid & 31, nq = tid >> 5;
    float bx = sB[2 * dq], by = sB[2 * dq + 1];
    unsigned long long accX01 = pack2(bx, bx);
    unsigned long long accX23 = pack2(bx, bx);
    unsigned long long accY01 = pack2(by, by);
    unsigned long long accY23 = pack2(by, by);
#pragma unroll
    for (int k = 0; k < DD; k++) {
        int cb = (4 * nq) ^ (((k >> 3) & 7) << 2);   // undo store swizzle
        unsigned long long h01 = *reinterpret_cast<const unsigned long long*>(&sHT[k][cb]);
        unsigned long long h23 = *reinterpret_cast<const unsigned long long*>(&sHT[k][cb + 2]);
        float2 wv = *reinterpret_cast<const float2*>(&sW[k * DD + 2 * dq]);
        unsigned long long wx2 = pack2(wv.x, wv.x);
        unsigned long long wy2 = pack2(wv.y, wv.y);
        fma2(accX01, h01, wx2);
        fma2(accX23, h23, wx2);
        fma2(accY01, h01, wy2);
        fma2(accY23, h23, wy2);
    }
    float x0, x1, x2, x3, y0, y1, y2, y3;
    unpack2(accX01, x0, x1); unpack2(accX23, x2, x3);
    unpack2(accY01, y0, y1); unpack2(accY23, y2, y3);
    float cx[4] = {x0, x1, x2, x3};
    float cy[4] = {y0, y1, y2, y3};
#pragma unroll
    for (int i = 0; i < 4; i++) {
        int n = nodeBase + 4 * nq + i;
        if (n < NN) {
            if (OUT_HALF) {
                float sc = PRESCALE ? sDI[4 * nq + i] : 1.0f;
                ((__half2*)uout)[n * 32 + dq] =
                    __floats2half2_rn(sc * tanh_a(cx[i]), sc * tanh_a(cy[i]));
            } else {
                ((float2*)uout)[n * 32 + dq] =
                    make_float2(tanh_a(cx[i]), tanh_a(cy[i]));
            }
        }
    }
}

// ------------------- pooling + head -------------------
__global__ void k_pool(const float* __restrict__ h, const float* __restrict__ Wout,
                       const float* __restrict__ bout, float* __restrict__ out) {
    int g = (blockIdx.x * blockDim.x + threadIdx.x) >> 5;
    int lid = threadIdx.x & 31;
    if (g >= GG) return;
    long long gs = (long long)g * NN;
    int start = (int)((gs + GG - 1) / GG);
    int end = (int)((gs + NN + GG - 1) / GG);
    if (end > NN) end = NN;
    const float2* h2 = (const float2*)h;
    float2 mx = make_float2(-INFINITY, -INFINITY);
    float2 sm = make_float2(0.f, 0.f);
    for (int i = start; i < end; i++) {
        float2 v = h2[i * 32 + lid];
        mx.x = fmaxf(mx.x, v.x);
        mx.y = fmaxf(mx.y, v.y);
        sm.x += v.x;
        sm.y += v.y;
    }
    int cnt = end - start; if (cnt < 1) cnt = 1;
    float inv = 1.0f / (float)cnt;
    const float2* w2 = (const float2*)Wout;
    float2 wmx = w2[lid];
    float2 wmn = w2[32 + lid];
    float v = mx.x * wmx.x + mx.y * wmx.y
            + (sm.x * inv) * wmn.x + (sm.y * inv) * wmn.y;
#pragma unroll
    for (int o = 16; o; o >>= 1) v += __shfl_down_sync(0xffffffffu, v, o);
    if (lid == 0) out[g] = v + bout[0];
}

// ------------------- launch -------------------

extern "C" void kernel_launch(void* const* d_in, const int* in_sizes, int n_in,
                              void* d_out, int out_size) {
    const float* x    = (const float*)d_in[0];
    const int*   ei   = (const int*)d_in[1];
    const float* W0   = (const float*)d_in[3];
    const float* b0   = (const float*)d_in[4];
    const float* W1   = (const float*)d_in[5];
    const float* b1   = (const float*)d_in[6];
    const float* W2   = (const float*)d_in[7];
    const float* b2   = (const float*)d_in[8];
    const float* W3   = (const float*)d_in[9];
    const float* b3   = (const float*)d_in[10];
    const float* Wout = (const float*)d_in[11];
    const float* bout = (const float*)d_in[12];
    float* out = (float*)d_out;

    const int* erow = ei;        // sources
    const int* ecol = ei + EE;   // destinations

    float *hA, *hB;
    cudaGetSymbolAddress((void**)&hA, g_hA);
    cudaGetSymbolAddress((void**)&hB, g_hB);

    int eB8 = (EE / 8 + 255) / 256;   // 391: 8 edges/thread
    int gB = (NN + 63) / 64;          // 782
    int pB = (GG * 32 + 255) / 256;

    k_hist<<<eB8, 256>>>(ecol);
    k_scan<<<NBLK, 256>>>(x);
    k_fill<<<eB8, 256>>>(erow, ecol);

    k_layer0<<<gB, 512>>>(W0, b0, (__half2*)hA);
    k_layer<true, true><<<gB, 512>>>((const __half2*)hA, W1, b1, hB);
    k_layer<true, true><<<gB, 512>>>((const __half2*)hB, W2, b2, hA);
    k_layer<false, false><<<gB, 512>>>((const __half2*)hA, W3, b3, hB);

    k_pool<<<pB, 256>>>(hB, Wout, bout, out);
}

// round 11
// speedup vs baseline: 2.7264x; 1.2221x over previous
#include <cuda_runtime.h>
#include <cuda_fp16.h>
#include <math.h>

#define NN 50000
#define EE 800000
#define GG 1024
#define DD 64
#define DIN 9
#define NBLK ((NN + 255) / 256)    // 196

// ---- scratch ----
__device__ int   g_deg[NN];        // all-zero at entry; re-zeroed in k_fill each call
__device__ float g_dinv[NN];
__device__ int   g_rowptr[NN + 1];
__device__ int   g_cursor[NN];
__device__ int   g_csrsrc[EE];
__device__ unsigned long long g_blkDesc[NBLK];  // zeroed in k_hist each call
__device__ uint4 g_xs16[NN * 2];   // fp16 input features, 16 halves/node (9 used)
__device__ float g_hA[NN * DD];
__device__ float g_hB[NN * DD];

__device__ __forceinline__ float tanh_a(float x) {
    float y;
    asm("tanh.approx.f32 %0, %1;" : "=f"(y) : "f"(x));
    return y;
}
__device__ __forceinline__ int sel4(int4 v, int g) {
    return g == 0 ? v.x : (g == 1 ? v.y : (g == 2 ? v.z : v.w));
}
__device__ __forceinline__ unsigned int smem_u32(const void* p) {
    return (unsigned int)__cvta_generic_to_shared(p);
}
__device__ __forceinline__ void ldmx4(unsigned int& r0, unsigned int& r1,
                                      unsigned int& r2, unsigned int& r3, unsigned int a) {
    asm volatile("ldmatrix.sync.aligned.m8n8.x4.shared.b16 {%0,%1,%2,%3}, [%4];"
                 : "=r"(r0), "=r"(r1), "=r"(r2), "=r"(r3) : "r"(a));
}
__device__ __forceinline__ void ldmx4t(unsigned int& r0, unsigned int& r1,
                                       unsigned int& r2, unsigned int& r3, unsigned int a) {
    asm volatile("ldmatrix.sync.aligned.m8n8.x4.trans.shared.b16 {%0,%1,%2,%3}, [%4];"
                 : "=r"(r0), "=r"(r1), "=r"(r2), "=r"(r3) : "r"(a));
}
__device__ __forceinline__ void mma16816(float* c, unsigned int a0, unsigned int a1,
                                         unsigned int a2, unsigned int a3,
                                         unsigned int b0, unsigned int b1) {
    asm volatile("mma.sync.aligned.m16n8k16.row.col.f32.f16.f16.f32 "
                 "{%0,%1,%2,%3}, {%4,%5,%6,%7}, {%8,%9}, {%0,%1,%2,%3};"
                 : "+f"(c[0]), "+f"(c[1]), "+f"(c[2]), "+f"(c[3])
                 : "r"(a0), "r"(a1), "r"(a2), "r"(a3), "r"(b0), "r"(b1));
}

// ------------------- preprocessing -------------------

__global__ void k_hist(const int* __restrict__ col) {
    int i = blockIdx.x * blockDim.x + threadIdx.x;
    if (i < NBLK) g_blkDesc[i] = 0ULL;
    long long base = (long long)i * 8;
    if (base < EE) {
        int4 a = reinterpret_cast<const int4*>(col)[i * 2];
        int4 b = reinterpret_cast<const int4*>(col)[i * 2 + 1];
        atomicAdd(&g_deg[a.x], 1); atomicAdd(&g_deg[a.y], 1);
        atomicAdd(&g_deg[a.z], 1); atomicAdd(&g_deg[a.w], 1);
        atomicAdd(&g_deg[b.x], 1); atomicAdd(&g_deg[b.y], 1);
        atomicAdd(&g_deg[b.z], 1); atomicAdd(&g_deg[b.w], 1);
    }
}

__global__ void k_scan(const float* __restrict__ x) {
    __shared__ int wsum[8];
    __shared__ int sprefix;
    int b = blockIdx.x, t = threadIdx.x;
    int i = b * 256 + t;
    int lane = t & 31, w = t >> 5;
    int v = (i < NN) ? g_deg[i] : 0;
    int s = v;
#pragma unroll
    for (int o = 1; o < 32; o <<= 1) {
        int u = __shfl_up_sync(~0u, s, o);
        if (lane >= o) s += u;
    }
    if (lane == 31) wsum[w] = s;
    __syncthreads();
    if (w == 0) {
        int ws = (lane < 8) ? wsum[lane] : 0;
#pragma unroll
        for (int o = 1; o < 8; o <<= 1) {
            int u = __shfl_up_sync(0xffu, ws, o);
            if (lane >= o) ws += u;
        }
        if (lane < 8) wsum[lane] = ws;
    }
    __syncthreads();
    int total = wsum[7];
    if (t == 0) {
        if (b == 0) {
            atomicExch(&g_blkDesc[0], ((unsigned long long)total << 2) | 2ULL);
            sprefix = 0;
        } else {
            atomicExch(&g_blkDesc[b], ((unsigned long long)total << 2) | 1ULL);
            int run = 0;
            for (int j = b - 1; j >= 0; j--) {
                unsigned long long d;
                do { d = *((volatile unsigned long long*)&g_blkDesc[j]); } while ((d & 3ULL) == 0ULL);
                run += (int)(d >> 2);
                if ((d & 3ULL) == 2ULL) break;
            }
            sprefix = run;
            atomicExch(&g_blkDesc[b], ((unsigned long long)(total + run) << 2) | 2ULL);
        }
    }
    __syncthreads();
    int excl = sprefix + (w > 0 ? wsum[w - 1] : 0) + (s - v);
    if (i < NN) {
        g_rowptr[i] = excl;
        g_cursor[i] = excl;
        float di = rsqrtf((float)v + 1.0f);  // +1 self loop
        g_dinv[i] = di;
        __half2* xo = (__half2*)g_xs16;
        float f[10];
#pragma unroll
        for (int c = 0; c < DIN; c++) f[c] = di * x[i * DIN + c];
        f[9] = 0.f;
#pragma unroll
        for (int j = 0; j < 5; j++)
            xo[i * 8 + j] = __floats2half2_rn(f[2 * j], f[2 * j + 1]);
#pragma unroll
        for (int j = 5; j < 8; j++)
            xo[i * 8 + j] = __floats2half2_rn(0.f, 0.f);
    }
    if (i == 0) g_rowptr[NN] = EE;
}

__global__ void k_fill(const int* __restrict__ row, const int* __restrict__ col) {
    int i = blockIdx.x * blockDim.x + threadIdx.x;
    if (i < NN) g_deg[i] = 0;
    long long base = (long long)i * 8;
    if (base < EE) {
        int4 ra = reinterpret_cast<const int4*>(row)[i * 2];
        int4 rb = reinterpret_cast<const int4*>(row)[i * 2 + 1];
        int4 ca = reinterpret_cast<const int4*>(col)[i * 2];
        int4 cb = reinterpret_cast<const int4*>(col)[i * 2 + 1];
        g_csrsrc[atomicAdd(&g_cursor[ca.x], 1)] = ra.x;
        g_csrsrc[atomicAdd(&g_cursor[ca.y], 1)] = ra.y;
        g_csrsrc[atomicAdd(&g_cursor[ca.z], 1)] = ra.z;
        g_csrsrc[atomicAdd(&g_cursor[ca.w], 1)] = ra.w;
        g_csrsrc[atomicAdd(&g_cursor[cb.x], 1)] = rb.x;
        g_csrsrc[atomicAdd(&g_cursor[cb.y], 1)] = rb.y;
        g_csrsrc[atomicAdd(&g_cursor[cb.z], 1)] = rb.z;
        g_csrsrc[atomicAdd(&g_cursor[cb.w], 1)] = rb.w;
    }
}

// accumulate 8 half cols from a uint4 into a0..a7
#define ACC8(q)                                                              \
    { float2 f;                                                              \
      f = __half22float2(*(const __half2*)&(q).x); a0 += f.x; a1 += f.y;     \
      f = __half22float2(*(const __half2*)&(q).y); a2 += f.x; a3 += f.y;     \
      f = __half22float2(*(const __half2*)&(q).z); a4 += f.x; a5 += f.y;     \
      f = __half22float2(*(const __half2*)&(q).w); a6 += f.x; a7 += f.y; }

// ------------------- fused layer 0: fp16 xs, 8 nbrs/instr gather + FFMA GEMM -------------------

__global__ void __launch_bounds__(512) k_layer0(const float* __restrict__ W0,
                                                const float* __restrict__ b0,
                                                __half2* __restrict__ uout) {
    __shared__ float sW[DIN * DD];
    __shared__ float sHT[16][68];   // [feature][node]
    __shared__ float sB[DD];
    __shared__ float sDI[64];
    int tid = threadIdx.x;
    int nodeBase = blockIdx.x * 64;
    for (int i = tid; i < DIN * DD; i += 512) sW[i] = W0[i];
    if (tid < DD) sB[tid] = b0[tid];
    int w = tid >> 5, lid = tid & 31;
    int hw = lid >> 4;       // node of pair
    int sl = lid & 15;
    int g = sl >> 1;         // neighbor slot (0..7)
    int c2 = sl & 1;         // uint4 column (halves 8c2..8c2+7)
    const uint4* xs4 = (const uint4*)g_xs16;
#pragma unroll
    for (int pass = 0; pass < 2; pass++) {
        int local = w * 4 + pass * 2 + hw;
        int node = nodeBase + local;
        float a0 = 0.f, a1 = 0.f, a2 = 0.f, a3 = 0.f;
        float a4 = 0.f, a5 = 0.f, a6 = 0.f, a7 = 0.f;
        float di = 0.f;
        if (node < NN) {
            di = g_dinv[node];
            int e = g_rowptr[node], e1 = g_rowptr[node + 1];
            int rem = e1 - e;
            int mis = (8 - (e & 7)) & 7; if (mis > rem) mis = rem;
            if (g < mis) { uint4 q = xs4[g_csrsrc[e + g] * 2 + c2]; ACC8(q); }
            e += mis;
            for (; e + 8 <= e1; e += 8) {
                int4 iA = *reinterpret_cast<const int4*>(&g_csrsrc[e]);
                int4 iB = *reinterpret_cast<const int4*>(&g_csrsrc[e + 4]);
                int s = (g < 4) ? sel4(iA, g) : sel4(iB, g - 4);
                uint4 q = xs4[s * 2 + c2]; ACC8(q);
            }
            int rem2 = e1 - e;
            if (g < rem2) { uint4 q = xs4[g_csrsrc[e + g] * 2 + c2]; ACC8(q); }
        }
        // merge the 8 neighbor slots (within 16-lane segment, same c2 parity)
#pragma unroll
        for (int o = 8; o >= 2; o >>= 1) {
            a0 += __shfl_down_sync(~0u, a0, o, 16);
            a1 += __shfl_down_sync(~0u, a1, o, 16);
            a2 += __shfl_down_sync(~0u, a2, o, 16);
            a3 += __shfl_down_sync(~0u, a3, o, 16);
            a4 += __shfl_down_sync(~0u, a4, o, 16);
            a5 += __shfl_down_sync(~0u, a5, o, 16);
            a6 += __shfl_down_sync(~0u, a6, o, 16);
            a7 += __shfl_down_sync(~0u, a7, o, 16);
        }
        if (sl < 2) {
            if (node < NN) {
                uint4 qs = xs4[node * 2 + sl];   // self (sl == c2 here)
                float2 f;
                f = __half22float2(*(const __half2*)&qs.x); a0 = di * (a0 + f.x); a1 = di * (a1 + f.y);
                f = __half22float2(*(const __half2*)&qs.y); a2 = di * (a2 + f.x); a3 = di * (a3 + f.y);
                f = __half22float2(*(const __half2*)&qs.z); a4 = di * (a4 + f.x); a5 = di * (a5 + f.y);
                f = __half22float2(*(const __half2*)&qs.w); a6 = di * (a6 + f.x); a7 = di * (a7 + f.y);
            }
            sHT[8 * sl + 0][local] = a0;
            sHT[8 * sl + 1][local] = a1;
            sHT[8 * sl + 2][local] = a2;
            sHT[8 * sl + 3][local] = a3;
            sHT[8 * sl + 4][local] = a4;
            sHT[8 * sl + 5][local] = a5;
            sHT[8 * sl + 6][local] = a6;
            sHT[8 * sl + 7][local] = a7;
            if (sl == 0) sDI[local] = di;
        }
    }
    __syncthreads();
    int dq = tid & 31, nq = tid >> 5;
    float acc[4][2];
#pragma unroll
    for (int i = 0; i < 4; i++) { acc[i][0] = sB[2 * dq]; acc[i][1] = sB[2 * dq + 1]; }
#pragma unroll
    for (int k = 0; k < DIN; k++) {
        float4 h4 = *reinterpret_cast<const float4*>(&sHT[k][4 * nq]);
        float2 w2 = *reinterpret_cast<const float2*>(&sW[k * DD + 2 * dq]);
        acc[0][0] += h4.x * w2.x; acc[0][1] += h4.x * w2.y;
        acc[1][0] += h4.y * w2.x; acc[1][1] += h4.y * w2.y;
        acc[2][0] += h4.z * w2.x; acc[2][1] += h4.z * w2.y;
        acc[3][0] += h4.w * w2.x; acc[3][1] += h4.w * w2.y;
    }
#pragma unroll
    for (int i = 0; i < 4; i++) {
        int n = nodeBase + 4 * nq + i;
        if (n < NN) {
            float sc = sDI[4 * nq + i];
            uout[n * 32 + dq] = __floats2half2_rn(sc * tanh_a(acc[i][0]),
                                                  sc * tanh_a(acc[i][1]));
        }
    }
}

// ------------------- fused layer: wide-lane gather + fp16 MMA GEMM -------------------

template <bool OUT_HALF, bool PRESCALE>
__global__ void __launch_bounds__(512) k_layer(const __half2* __restrict__ uin,
                                               const float* __restrict__ W,
                                               const float* __restrict__ bias,
                                               void* __restrict__ uout) {
    __shared__ __half sA[64][72];    // agg tile fp16, stride 72 (ldmatrix conflict-free)
    __shared__ __half sBW[64][72];   // W fp16 [k][col]
    __shared__ float  sB[DD];
    __shared__ float  sDI[64];
    int tid = threadIdx.x;
    int nodeBase = blockIdx.x * 64;
    for (int i = tid; i < DD * DD; i += 512)
        sBW[i >> 6][i & 63] = __float2half(W[i]);
    if (tid < DD) sB[tid] = bias[tid];
    int w = tid >> 5, lid = tid & 31;
    int hw = lid >> 4;      // node of pair
    int sl = lid & 15;
    int g8 = sl >> 3;       // neighbor slot (0/1)
    int c8 = sl & 7;        // uint4 col (half-cols 8c8..8c8+7)
    const uint4* u4 = (const uint4*)uin;
#pragma unroll
    for (int pass = 0; pass < 2; pass++) {
        int local = w * 4 + pass * 2 + hw;
        int node = nodeBase + local;
        float a0 = 0.f, a1 = 0.f, a2 = 0.f, a3 = 0.f;
        float a4 = 0.f, a5 = 0.f, a6 = 0.f, a7 = 0.f;
        float di = 0.f;
        if (node < NN) {
            di = g_dinv[node];
            int e = g_rowptr[node], e1 = g_rowptr[node + 1];
            int mis = (4 - (e & 3)) & 3;
            int rem = e1 - e; if (mis > rem) mis = rem;
            if (mis & 1) {
                if (g8 == 0) { uint4 q = u4[g_csrsrc[e] * 8 + c8]; ACC8(q); }
                e += 1;
            }
            if (mis & 2) {
                uint4 q = u4[g_csrsrc[e + g8] * 8 + c8]; ACC8(q);
                e += 2;
            }
            for (; e + 8 <= e1; e += 8) {
                int4 iA = *reinterpret_cast<const int4*>(&g_csrsrc[e]);
                int4 iB = *reinterpret_cast<const int4*>(&g_csrsrc[e + 4]);
                uint4 q0 = u4[(g8 ? iA.y : iA.x) * 8 + c8];
                uint4 q1 = u4[(g8 ? iA.w : iA.z) * 8 + c8];
                uint4 q2 = u4[(g8 ? iB.y : iB.x) * 8 + c8];
                uint4 q3 = u4[(g8 ? iB.w : iB.z) * 8 + c8];
                ACC8(q0); ACC8(q1); ACC8(q2); ACC8(q3);
            }
            if (e + 4 <= e1) {
                int4 iA = *reinterpret_cast<const int4*>(&g_csrsrc[e]);
                uint4 q0 = u4[(g8 ? iA.y : iA.x) * 8 + c8];
                uint4 q1 = u4[(g8 ? iA.w : iA.z) * 8 + c8];
                ACC8(q0); ACC8(q1);
                e += 4;
            }
            if (e + 2 <= e1) {
                uint4 q = u4[g_csrsrc[e + g8] * 8 + c8]; ACC8(q);
                e += 2;
            }
            if (e < e1 && g8 == 0) {
                uint4 q = u4[g_csrsrc[e] * 8 + c8]; ACC8(q);
            }
        }
        // merge the two neighbor-slot groups
        a0 += __shfl_down_sync(~0u, a0, 8, 16);
        a1 += __shfl_down_sync(~0u, a1, 8, 16);
        a2 += __shfl_down_sync(~0u, a2, 8, 16);
        a3 += __shfl_down_sync(~0u, a3, 8, 16);
        a4 += __shfl_down_sync(~0u, a4, 8, 16);
        a5 += __shfl_down_sync(~0u, a5, 8, 16);
        a6 += __shfl_down_sync(~0u, a6, 8, 16);
        a7 += __shfl_down_sync(~0u, a7, 8, 16);
        if (sl < 8) {
            if (node < NN) {
                uint4 qs = u4[node * 8 + c8];
                float2 f;
                f = __half22float2(*(const __half2*)&qs.x); a0 = di * (a0 + f.x); a1 = di * (a1 + f.y);
                f = __half22float2(*(const __half2*)&qs.y); a2 = di * (a2 + f.x); a3 = di * (a3 + f.y);
                f = __half22float2(*(const __half2*)&qs.z); a4 = di * (a4 + f.x); a5 = di * (a5 + f.y);
                f = __half22float2(*(const __half2*)&qs.w); a6 = di * (a6 + f.x); a7 = di * (a7 + f.y);
            }
            __half2 h0 = __floats2half2_rn(a0, a1);
            __half2 h1 = __floats2half2_rn(a2, a3);
            __half2 h2 = __floats2half2_rn(a4, a5);
            __half2 h3 = __floats2half2_rn(a6, a7);
            uint4 q;
            q.x = *reinterpret_cast<unsigned int*>(&h0);
            q.y = *reinterpret_cast<unsigned int*>(&h1);
            q.z = *reinterpret_cast<unsigned int*>(&h2);
            q.w = *reinterpret_cast<unsigned int*>(&h3);
            *reinterpret_cast<uint4*>(&sA[local][c8 * 8]) = q;
            if (c8 == 0) sDI[local] = di;
        }
    }
    __syncthreads();
    // MMA: warp (mi,ni) computes nodes 16mi..16mi+15 x cols 16ni..16ni+15
    int lane = tid & 31;
    int wid = tid >> 5;
    int mi = wid >> 2, ni = wid & 3;
    float c0[4] = {0.f, 0.f, 0.f, 0.f};
    float c1[4] = {0.f, 0.f, 0.f, 0.f};
    unsigned int aBase = smem_u32(&sA[16 * mi + (lane & 15)][(lane >> 4) * 8]);
    unsigned int bBase = smem_u32(&sBW[lane & 15][16 * ni + ((lane >> 4) << 3)]);
#pragma unroll
    for (int kk = 0; kk < 4; kk++) {
        unsigned int a0, a1, a2, a3, b0, b1, b2, b3;
        ldmx4(a0, a1, a2, a3, aBase + kk * 32);          // +16 halves in k
        ldmx4t(b0, b1, b2, b3, bBase + kk * 16 * 144);   // +16 rows of 144 B
        mma16816(c0, a0, a1, a2, a3, b0, b1);
        mma16816(c1, a0, a1, a2, a3, b2, b3);
    }
    int r0 = 16 * mi + (lane >> 2);
    int cb0 = 16 * ni + (lane & 3) * 2;
#pragma unroll
    for (int t2 = 0; t2 < 2; t2++) {
        const float* cc = t2 ? c1 : c0;
        int cb = cb0 + t2 * 8;
        float bx = sB[cb], by = sB[cb + 1];
#pragma unroll
        for (int rh = 0; rh < 2; rh++) {
            int r = r0 + rh * 8;
            int n = nodeBase + r;
            if (n < NN) {
                float v0 = cc[2 * rh] + bx;
                float v1 = cc[2 * rh + 1] + by;
                if (OUT_HALF) {
                    float sc = PRESCALE ? sDI[r] : 1.0f;
                    ((__half2*)uout)[n * 32 + (cb >> 1)] =
                        __floats2half2_rn(sc * tanh_a(v0), sc * tanh_a(v1));
                } else {
                    ((float2*)uout)[n * 32 + (cb >> 1)] =
                        make_float2(tanh_a(v0), tanh_a(v1));
                }
            }
        }
    }
}

// ------------------- pooling + head -------------------
__global__ void k_pool(const float* __restrict__ h, const float* __restrict__ Wout,
                       const float* __restrict__ bout, float* __restrict__ out) {
    int g = (blockIdx.x * blockDim.x + threadIdx.x) >> 5;
    int lid = threadIdx.x & 31;
    if (g >= GG) return;
    long long gs = (long long)g * NN;
    int start = (int)((gs + GG - 1) / GG);
    int end = (int)((gs + NN + GG - 1) / GG);
    if (end > NN) end = NN;
    const float2* h2 = (const float2*)h;
    float2 mx = make_float2(-INFINITY, -INFINITY);
    float2 sm = make_float2(0.f, 0.f);
    for (int i = start; i < end; i++) {
        float2 v = h2[i * 32 + lid];
        mx.x = fmaxf(mx.x, v.x);
        mx.y = fmaxf(mx.y, v.y);
        sm.x += v.x;
        sm.y += v.y;
    }
    int cnt = end - start; if (cnt < 1) cnt = 1;
    float inv = 1.0f / (float)cnt;
    const float2* w2 = (const float2*)Wout;
    float2 wmx = w2[lid];
    float2 wmn = w2[32 + lid];
    float v = mx.x * wmx.x + mx.y * wmx.y
            + (sm.x * inv) * wmn.x + (sm.y * inv) * wmn.y;
#pragma unroll
    for (int o = 16; o; o >>= 1) v += __shfl_down_sync(0xffffffffu, v, o);
    if (lid == 0) out[g] = v + bout[0];
}

// ------------------- launch -------------------

extern "C" void kernel_launch(void* const* d_in, const int* in_sizes, int n_in,
                              void* d_out, int out_size) {
    const float* x    = (const float*)d_in[0];
    const int*   ei   = (const int*)d_in[1];
    const float* W0   = (const float*)d_in[3];
    const float* b0   = (const float*)d_in[4];
    const float* W1   = (const float*)d_in[5];
    const float* b1   = (const float*)d_in[6];
    const float* W2   = (const float*)d_in[7];
    const float* b2   = (const float*)d_in[8];
    const float* W3   = (const float*)d_in[9];
    const float* b3   = (const float*)d_in[10];
    const float* Wout = (const float*)d_in[11];
    const float* bout = (const float*)d_in[12];
    float* out = (float*)d_out;

    const int* erow = ei;        // sources
    const int* ecol = ei + EE;   // destinations

    float *hA, *hB;
    cudaGetSymbolAddress((void**)&hA, g_hA);
    cudaGetSymbolAddress((void**)&hB, g_hB);

    int eB8 = (EE / 8 + 255) / 256;   // 391
    int gB = (NN + 63) / 64;          // 782
    int pB = (GG * 32 + 255) / 256;

    k_hist<<<eB8, 256>>>(ecol);
    k_scan<<<NBLK, 256>>>(x);
    k_fill<<<eB8, 256>>>(erow, ecol);

    k_layer0<<<gB, 512>>>(W0, b0, (__half2*)hA);
    k_layer<true, true><<<gB, 512>>>((const __half2*)hA, W1, b1, hB);
    k_layer<true, true><<<gB, 512>>>((const __half2*)hB, W2, b2, hA);
    k_layer<false, false><<<gB, 512>>>((const __half2*)hA, W3, b3, hB);

    k_pool<<<pB, 256>>>(hB, Wout, bout, out);
}

// round 12
// speedup vs baseline: 2.8548x; 1.0471x over previous
#include <cuda_runtime.h>
#include <cuda_fp16.h>
#include <math.h>

#define NN 50000
#define EE 800000
#define GG 1024
#define DD 64
#define DIN 9
#define NBLK ((NN + 255) / 256)    // 196

// ---- scratch ----
__device__ int   g_deg[NN];        // all-zero at entry; re-zeroed in k_fill each call
__device__ float g_dinv[NN];
__device__ int   g_rowptr[NN + 1];
__device__ int   g_cursor[NN];
__device__ int   g_csrsrc[EE];
__device__ unsigned long long g_blkDesc[NBLK];  // zeroed in k_hist each call
__device__ uint4 g_xs16[NN * 2];   // fp16 input features, 16 halves/node (9 used)
__device__ float g_hA[NN * DD];
__device__ float g_hB[NN * DD];

__device__ __forceinline__ float tanh_a(float x) {
    float y;
    asm("tanh.approx.f32 %0, %1;" : "=f"(y) : "f"(x));
    return y;
}
__device__ __forceinline__ int sel4(int4 v, int g) {
    return g == 0 ? v.x : (g == 1 ? v.y : (g == 2 ? v.z : v.w));
}
__device__ __forceinline__ unsigned int smem_u32(const void* p) {
    return (unsigned int)__cvta_generic_to_shared(p);
}
__device__ __forceinline__ void ldmx4(unsigned int& r0, unsigned int& r1,
                                      unsigned int& r2, unsigned int& r3, unsigned int a) {
    asm volatile("ldmatrix.sync.aligned.m8n8.x4.shared.b16 {%0,%1,%2,%3}, [%4];"
                 : "=r"(r0), "=r"(r1), "=r"(r2), "=r"(r3) : "r"(a));
}
__device__ __forceinline__ void ldmx4t(unsigned int& r0, unsigned int& r1,
                                       unsigned int& r2, unsigned int& r3, unsigned int a) {
    asm volatile("ldmatrix.sync.aligned.m8n8.x4.trans.shared.b16 {%0,%1,%2,%3}, [%4];"
                 : "=r"(r0), "=r"(r1), "=r"(r2), "=r"(r3) : "r"(a));
}
__device__ __forceinline__ void mma16816(float* c, unsigned int a0, unsigned int a1,
                                         unsigned int a2, unsigned int a3,
                                         unsigned int b0, unsigned int b1) {
    asm volatile("mma.sync.aligned.m16n8k16.row.col.f32.f16.f16.f32 "
                 "{%0,%1,%2,%3}, {%4,%5,%6,%7}, {%8,%9}, {%0,%1,%2,%3};"
                 : "+f"(c[0]), "+f"(c[1]), "+f"(c[2]), "+f"(c[3])
                 : "r"(a0), "r"(a1), "r"(a2), "r"(a3), "r"(b0), "r"(b1));
}

#define H2C(p) (*(const __half2*)&(p))

// ------------------- preprocessing -------------------

__global__ void k_hist(const int* __restrict__ col) {
    int i = blockIdx.x * blockDim.x + threadIdx.x;
    if (i < NBLK) g_blkDesc[i] = 0ULL;
    long long base = (long long)i * 8;
    if (base < EE) {
        int4 a = reinterpret_cast<const int4*>(col)[i * 2];
        int4 b = reinterpret_cast<const int4*>(col)[i * 2 + 1];
        atomicAdd(&g_deg[a.x], 1); atomicAdd(&g_deg[a.y], 1);
        atomicAdd(&g_deg[a.z], 1); atomicAdd(&g_deg[a.w], 1);
        atomicAdd(&g_deg[b.x], 1); atomicAdd(&g_deg[b.y], 1);
        atomicAdd(&g_deg[b.z], 1); atomicAdd(&g_deg[b.w], 1);
    }
}

__global__ void k_scan(const float* __restrict__ x) {
    __shared__ int wsum[8];
    __shared__ int sprefix;
    int b = blockIdx.x, t = threadIdx.x;
    int i = b * 256 + t;
    int lane = t & 31, w = t >> 5;
    int v = (i < NN) ? g_deg[i] : 0;
    int s = v;
#pragma unroll
    for (int o = 1; o < 32; o <<= 1) {
        int u = __shfl_up_sync(~0u, s, o);
        if (lane >= o) s += u;
    }
    if (lane == 31) wsum[w] = s;
    __syncthreads();
    if (w == 0) {
        int ws = (lane < 8) ? wsum[lane] : 0;
#pragma unroll
        for (int o = 1; o < 8; o <<= 1) {
            int u = __shfl_up_sync(0xffu, ws, o);
            if (lane >= o) ws += u;
        }
        if (lane < 8) wsum[lane] = ws;
    }
    __syncthreads();
    int total = wsum[7];
    if (t == 0) {
        if (b == 0) {
            atomicExch(&g_blkDesc[0], ((unsigned long long)total << 2) | 2ULL);
            sprefix = 0;
        } else {
            atomicExch(&g_blkDesc[b], ((unsigned long long)total << 2) | 1ULL);
            int run = 0;
            for (int j = b - 1; j >= 0; j--) {
                unsigned long long d;
                do { d = *((volatile unsigned long long*)&g_blkDesc[j]); } while ((d & 3ULL) == 0ULL);
                run += (int)(d >> 2);
                if ((d & 3ULL) == 2ULL) break;
            }
            sprefix = run;
            atomicExch(&g_blkDesc[b], ((unsigned long long)(total + run) << 2) | 2ULL);
        }
    }
    __syncthreads();
    int excl = sprefix + (w > 0 ? wsum[w - 1] : 0) + (s - v);
    if (i < NN) {
        g_rowptr[i] = excl;
        g_cursor[i] = excl;
        float di = rsqrtf((float)v + 1.0f);  // +1 self loop
        g_dinv[i] = di;
        __half2* xo = (__half2*)g_xs16;
        float f[10];
#pragma unroll
        for (int c = 0; c < DIN; c++) f[c] = di * x[i * DIN + c];
        f[9] = 0.f;
#pragma unroll
        for (int j = 0; j < 5; j++)
            xo[i * 8 + j] = __floats2half2_rn(f[2 * j], f[2 * j + 1]);
#pragma unroll
        for (int j = 5; j < 8; j++)
            xo[i * 8 + j] = __floats2half2_rn(0.f, 0.f);
    }
    if (i == 0) g_rowptr[NN] = EE;
}

__global__ void k_fill(const int* __restrict__ row, const int* __restrict__ col) {
    int i = blockIdx.x * blockDim.x + threadIdx.x;
    if (i < NN) g_deg[i] = 0;
    long long base = (long long)i * 8;
    if (base < EE) {
        int4 ra = reinterpret_cast<const int4*>(row)[i * 2];
        int4 rb = reinterpret_cast<const int4*>(row)[i * 2 + 1];
        int4 ca = reinterpret_cast<const int4*>(col)[i * 2];
        int4 cb = reinterpret_cast<const int4*>(col)[i * 2 + 1];
        g_csrsrc[atomicAdd(&g_cursor[ca.x], 1)] = ra.x;
        g_csrsrc[atomicAdd(&g_cursor[ca.y], 1)] = ra.y;
        g_csrsrc[atomicAdd(&g_cursor[ca.z], 1)] = ra.z;
        g_csrsrc[atomicAdd(&g_cursor[ca.w], 1)] = ra.w;
        g_csrsrc[atomicAdd(&g_cursor[cb.x], 1)] = rb.x;
        g_csrsrc[atomicAdd(&g_cursor[cb.y], 1)] = rb.y;
        g_csrsrc[atomicAdd(&g_cursor[cb.z], 1)] = rb.z;
        g_csrsrc[atomicAdd(&g_cursor[cb.w], 1)] = rb.w;
    }
}

// fp32-path accumulate (remainder edges): 8 half cols from a uint4 into a0..a7
#define ACC8(q)                                                              \
    { float2 f;                                                              \
      f = __half22float2(H2C((q).x)); a0 += f.x; a1 += f.y;                  \
      f = __half22float2(H2C((q).y)); a2 += f.x; a3 += f.y;                  \
      f = __half22float2(H2C((q).z)); a4 += f.x; a5 += f.y;                  \
      f = __half22float2(H2C((q).w)); a6 += f.x; a7 += f.y; }

// fp16 pair (qa+qb) then flush to fp32 accumulators
#define ACCPAIR(qa, qb)                                                      \
    { __half2 v0 = __hadd2(H2C((qa).x), H2C((qb).x));                        \
      __half2 v1 = __hadd2(H2C((qa).y), H2C((qb).y));                        \
      __half2 v2 = __hadd2(H2C((qa).z), H2C((qb).z));                        \
      __half2 v3 = __hadd2(H2C((qa).w), H2C((qb).w));                        \
      float2 f;                                                              \
      f = __half22float2(v0); a0 += f.x; a1 += f.y;                          \
      f = __half22float2(v1); a2 += f.x; a3 += f.y;                          \
      f = __half22float2(v2); a4 += f.x; a5 += f.y;                          \
      f = __half22float2(v3); a6 += f.x; a7 += f.y; }

// fp16 tree (q0+q1)+(q2+q3) then flush to fp32 accumulators
#define ACCTREE4(q0, q1, q2, q3)                                             \
    { __half2 t0 = __hadd2(H2C((q0).x), H2C((q1).x));                        \
      __half2 t1 = __hadd2(H2C((q0).y), H2C((q1).y));                        \
      __half2 t2 = __hadd2(H2C((q0).z), H2C((q1).z));                        \
      __half2 t3 = __hadd2(H2C((q0).w), H2C((q1).w));                        \
      __half2 u0 = __hadd2(H2C((q2).x), H2C((q3).x));                        \
      __half2 u1 = __hadd2(H2C((q2).y), H2C((q3).y));                        \
      __half2 u2 = __hadd2(H2C((q2).z), H2C((q3).z));                        \
      __half2 u3 = __hadd2(H2C((q2).w), H2C((q3).w));                        \
      __half2 v0 = __hadd2(t0, u0);                                          \
      __half2 v1 = __hadd2(t1, u1);                                          \
      __half2 v2 = __hadd2(t2, u2);                                          \
      __half2 v3 = __hadd2(t3, u3);                                          \
      float2 f;                                                              \
      f = __half22float2(v0); a0 += f.x; a1 += f.y;                          \
      f = __half22float2(v1); a2 += f.x; a3 += f.y;                          \
      f = __half22float2(v2); a4 += f.x; a5 += f.y;                          \
      f = __half22float2(v3); a6 += f.x; a7 += f.y; }

// ------------------- fused layer 0: fp16 xs, 8 nbrs/instr gather + FFMA GEMM -------------------

__global__ void __launch_bounds__(512) k_layer0(const float* __restrict__ W0,
                                                const float* __restrict__ b0,
                                                __half2* __restrict__ uout) {
    __shared__ float sW[DIN * DD];
    __shared__ float sHT[16][68];   // [feature][node]
    __shared__ float sB[DD];
    __shared__ float sDI[64];
    int tid = threadIdx.x;
    int nodeBase = blockIdx.x * 64;
    for (int i = tid; i < DIN * DD; i += 512) sW[i] = W0[i];
    if (tid < DD) sB[tid] = b0[tid];
    int w = tid >> 5, lid = tid & 31;
    int hw = lid >> 4;       // node of pair
    int sl = lid & 15;
    int g = sl >> 1;         // neighbor slot (0..7)
    int c2 = sl & 1;         // uint4 column (halves 8c2..8c2+7)
    const uint4* xs4 = (const uint4*)g_xs16;
#pragma unroll
    for (int pass = 0; pass < 2; pass++) {
        int local = w * 4 + pass * 2 + hw;
        int node = nodeBase + local;
        float a0 = 0.f, a1 = 0.f, a2 = 0.f, a3 = 0.f;
        float a4 = 0.f, a5 = 0.f, a6 = 0.f, a7 = 0.f;
        float di = 0.f;
        if (node < NN) {
            di = g_dinv[node];
            int e = g_rowptr[node], e1 = g_rowptr[node + 1];
            int rem = e1 - e;
            int mis = (8 - (e & 7)) & 7; if (mis > rem) mis = rem;
            if (g < mis) { uint4 q = xs4[g_csrsrc[e + g] * 2 + c2]; ACC8(q); }
            e += mis;
            // 16-wide: two 8-neighbor groups paired in fp16
            for (; e + 16 <= e1; e += 16) {
                int4 iA0 = *reinterpret_cast<const int4*>(&g_csrsrc[e]);
                int4 iB0 = *reinterpret_cast<const int4*>(&g_csrsrc[e + 4]);
                int4 iA1 = *reinterpret_cast<const int4*>(&g_csrsrc[e + 8]);
                int4 iB1 = *reinterpret_cast<const int4*>(&g_csrsrc[e + 12]);
                int s0 = (g < 4) ? sel4(iA0, g) : sel4(iB0, g - 4);
                int s1 = (g < 4) ? sel4(iA1, g) : sel4(iB1, g - 4);
                uint4 qa = xs4[s0 * 2 + c2];
                uint4 qb = xs4[s1 * 2 + c2];
                ACCPAIR(qa, qb);
            }
            if (e + 8 <= e1) {
                int4 iA = *reinterpret_cast<const int4*>(&g_csrsrc[e]);
                int4 iB = *reinterpret_cast<const int4*>(&g_csrsrc[e + 4]);
                int s = (g < 4) ? sel4(iA, g) : sel4(iB, g - 4);
                uint4 q = xs4[s * 2 + c2]; ACC8(q);
                e += 8;
            }
            int rem2 = e1 - e;
            if (g < rem2) { uint4 q = xs4[g_csrsrc[e + g] * 2 + c2]; ACC8(q); }
        }
        // merge the 8 neighbor slots (within 16-lane segment, same c2 parity)
#pragma unroll
        for (int o = 8; o >= 2; o >>= 1) {
            a0 += __shfl_down_sync(~0u, a0, o, 16);
            a1 += __shfl_down_sync(~0u, a1, o, 16);
            a2 += __shfl_down_sync(~0u, a2, o, 16);
            a3 += __shfl_down_sync(~0u, a3, o, 16);
            a4 += __shfl_down_sync(~0u, a4, o, 16);
            a5 += __shfl_down_sync(~0u, a5, o, 16);
            a6 += __shfl_down_sync(~0u, a6, o, 16);
            a7 += __shfl_down_sync(~0u, a7, o, 16);
        }
        if (sl < 2) {
            if (node < NN) {
                uint4 qs = xs4[node * 2 + sl];   // self (sl == c2 here)
                float2 f;
                f = __half22float2(H2C(qs.x)); a0 = di * (a0 + f.x); a1 = di * (a1 + f.y);
                f = __half22float2(H2C(qs.y)); a2 = di * (a2 + f.x); a3 = di * (a3 + f.y);
                f = __half22float2(H2C(qs.z)); a4 = di * (a4 + f.x); a5 = di * (a5 + f.y);
                f = __half22float2(H2C(qs.w)); a6 = di * (a6 + f.x); a7 = di * (a7 + f.y);
            }
            sHT[8 * sl + 0][local] = a0;
            sHT[8 * sl + 1][local] = a1;
            sHT[8 * sl + 2][local] = a2;
            sHT[8 * sl + 3][local] = a3;
            sHT[8 * sl + 4][local] = a4;
            sHT[8 * sl + 5][local] = a5;
            sHT[8 * sl + 6][local] = a6;
            sHT[8 * sl + 7][local] = a7;
            if (sl == 0) sDI[local] = di;
        }
    }
    __syncthreads();
    int dq = tid & 31, nq = tid >> 5;
    float acc[4][2];
#pragma unroll
    for (int i = 0; i < 4; i++) { acc[i][0] = sB[2 * dq]; acc[i][1] = sB[2 * dq + 1]; }
#pragma unroll
    for (int k = 0; k < DIN; k++) {
        float4 h4 = *reinterpret_cast<const float4*>(&sHT[k][4 * nq]);
        float2 w2 = *reinterpret_cast<const float2*>(&sW[k * DD + 2 * dq]);
        acc[0][0] += h4.x * w2.x; acc[0][1] += h4.x * w2.y;
        acc[1][0] += h4.y * w2.x; acc[1][1] += h4.y * w2.y;
        acc[2][0] += h4.z * w2.x; acc[2][1] += h4.z * w2.y;
        acc[3][0] += h4.w * w2.x; acc[3][1] += h4.w * w2.y;
    }
#pragma unroll
    for (int i = 0; i < 4; i++) {
        int n = nodeBase + 4 * nq + i;
        if (n < NN) {
            float sc = sDI[4 * nq + i];
            uout[n * 32 + dq] = __floats2half2_rn(sc * tanh_a(acc[i][0]),
                                                  sc * tanh_a(acc[i][1]));
        }
    }
}

// ------------------- fused layer: fp16-tree gather + fp16 MMA GEMM -------------------

template <bool OUT_HALF, bool PRESCALE>
__global__ void __launch_bounds__(512) k_layer(const __half2* __restrict__ uin,
                                               const float* __restrict__ W,
                                               const float* __restrict__ bias,
                                               void* __restrict__ uout) {
    __shared__ __half sA[64][72];    // agg tile fp16, stride 72 (ldmatrix conflict-free)
    __shared__ __half sBW[64][72];   // W fp16 [k][col]
    __shared__ float  sB[DD];
    __shared__ float  sDI[64];
    int tid = threadIdx.x;
    int nodeBase = blockIdx.x * 64;
    for (int i = tid; i < DD * DD; i += 512)
        sBW[i >> 6][i & 63] = __float2half(W[i]);
    if (tid < DD) sB[tid] = bias[tid];
    int w = tid >> 5, lid = tid & 31;
    int hw = lid >> 4;      // node of pair
    int sl = lid & 15;
    int g8 = sl >> 3;       // neighbor slot (0/1)
    int c8 = sl & 7;        // uint4 col (half-cols 8c8..8c8+7)
    const uint4* u4 = (const uint4*)uin;
#pragma unroll
    for (int pass = 0; pass < 2; pass++) {
        int local = w * 4 + pass * 2 + hw;
        int node = nodeBase + local;
        float a0 = 0.f, a1 = 0.f, a2 = 0.f, a3 = 0.f;
        float a4 = 0.f, a5 = 0.f, a6 = 0.f, a7 = 0.f;
        float di = 0.f;
        if (node < NN) {
            di = g_dinv[node];
            int e = g_rowptr[node], e1 = g_rowptr[node + 1];
            int mis = (4 - (e & 3)) & 3;
            int rem = e1 - e; if (mis > rem) mis = rem;
            if (mis & 1) {
                if (g8 == 0) { uint4 q = u4[g_csrsrc[e] * 8 + c8]; ACC8(q); }
                e += 1;
            }
            if (mis & 2) {
                uint4 q = u4[g_csrsrc[e + g8] * 8 + c8]; ACC8(q);
                e += 2;
            }
            // 8 edges per iter: 4 neighbor rows per lane group, fp16 tree
            for (; e + 8 <= e1; e += 8) {
                int4 iA = *reinterpret_cast<const int4*>(&g_csrsrc[e]);
                int4 iB = *reinterpret_cast<const int4*>(&g_csrsrc[e + 4]);
                uint4 q0 = u4[(g8 ? iA.y : iA.x) * 8 + c8];
                uint4 q1 = u4[(g8 ? iA.w : iA.z) * 8 + c8];
                uint4 q2 = u4[(g8 ? iB.y : iB.x) * 8 + c8];
                uint4 q3 = u4[(g8 ? iB.w : iB.z) * 8 + c8];
                ACCTREE4(q0, q1, q2, q3);
            }
            if (e + 4 <= e1) {
                int4 iA = *reinterpret_cast<const int4*>(&g_csrsrc[e]);
                uint4 q0 = u4[(g8 ? iA.y : iA.x) * 8 + c8];
                uint4 q1 = u4[(g8 ? iA.w : iA.z) * 8 + c8];
                ACCPAIR(q0, q1);
                e += 4;
            }
            if (e + 2 <= e1) {
                uint4 q = u4[g_csrsrc[e + g8] * 8 + c8]; ACC8(q);
                e += 2;
            }
            if (e < e1 && g8 == 0) {
                uint4 q = u4[g_csrsrc[e] * 8 + c8]; ACC8(q);
            }
        }
        // merge the two neighbor-slot groups
        a0 += __shfl_down_sync(~0u, a0, 8, 16);
        a1 += __shfl_down_sync(~0u, a1, 8, 16);
        a2 += __shfl_down_sync(~0u, a2, 8, 16);
        a3 += __shfl_down_sync(~0u, a3, 8, 16);
        a4 += __shfl_down_sync(~0u, a4, 8, 16);
        a5 += __shfl_down_sync(~0u, a5, 8, 16);
        a6 += __shfl_down_sync(~0u, a6, 8, 16);
        a7 += __shfl_down_sync(~0u, a7, 8, 16);
        if (sl < 8) {
            if (node < NN) {
                uint4 qs = u4[node * 8 + c8];
                float2 f;
                f = __half22float2(H2C(qs.x)); a0 = di * (a0 + f.x); a1 = di * (a1 + f.y);
                f = __half22float2(H2C(qs.y)); a2 = di * (a2 + f.x); a3 = di * (a3 + f.y);
                f = __half22float2(H2C(qs.z)); a4 = di * (a4 + f.x); a5 = di * (a5 + f.y);
                f = __half22float2(H2C(qs.w)); a6 = di * (a6 + f.x); a7 = di * (a7 + f.y);
            }
            __half2 h0 = __floats2half2_rn(a0, a1);
            __half2 h1 = __floats2half2_rn(a2, a3);
            __half2 h2 = __floats2half2_rn(a4, a5);
            __half2 h3 = __floats2half2_rn(a6, a7);
            uint4 q;
            q.x = *reinterpret_cast<unsigned int*>(&h0);
            q.y = *reinterpret_cast<unsigned int*>(&h1);
            q.z = *reinterpret_cast<unsigned int*>(&h2);
            q.w = *reinterpret_cast<unsigned int*>(&h3);
            *reinterpret_cast<uint4*>(&sA[local][c8 * 8]) = q;
            if (c8 == 0) sDI[local] = di;
        }
    }
    __syncthreads();
    // MMA: warp (mi,ni) computes nodes 16mi..16mi+15 x cols 16ni..16ni+15
    int lane = tid & 31;
    int wid = tid >> 5;
    int mi = wid >> 2, ni = wid & 3;
    float c0[4] = {0.f, 0.f, 0.f, 0.f};
    float c1[4] = {0.f, 0.f, 0.f, 0.f};
    unsigned int aBase = smem_u32(&sA[16 * mi + (lane & 15)][(lane >> 4) * 8]);
    unsigned int bBase = smem_u32(&sBW[lane & 15][16 * ni + ((lane >> 4) << 3)]);
#pragma unroll
    for (int kk = 0; kk < 4; kk++) {
        unsigned int a0, a1, a2, a3, b0, b1, b2, b3;
        ldmx4(a0, a1, a2, a3, aBase + kk * 32);          // +16 halves in k
        ldmx4t(b0, b1, b2, b3, bBase + kk * 16 * 144);   // +16 rows of 144 B
        mma16816(c0, a0, a1, a2, a3, b0, b1);
        mma16816(c1, a0, a1, a2, a3, b2, b3);
    }
    int r0 = 16 * mi + (lane >> 2);
    int cb0 = 16 * ni + (lane & 3) * 2;
#pragma unroll
    for (int t2 = 0; t2 < 2; t2++) {
        const float* cc = t2 ? c1 : c0;
        int cb = cb0 + t2 * 8;
        float bx = sB[cb], by = sB[cb + 1];
#pragma unroll
        for (int rh = 0; rh < 2; rh++) {
            int r = r0 + rh * 8;
            int n = nodeBase + r;
            if (n < NN) {
                float v0 = cc[2 * rh] + bx;
                float v1 = cc[2 * rh + 1] + by;
                if (OUT_HALF) {
                    float sc = PRESCALE ? sDI[r] : 1.0f;
                    ((__half2*)uout)[n * 32 + (cb >> 1)] =
                        __floats2half2_rn(sc * tanh_a(v0), sc * tanh_a(v1));
                } else {
                    ((float2*)uout)[n * 32 + (cb >> 1)] =
                        make_float2(tanh_a(v0), tanh_a(v1));
                }
            }
        }
    }
}

// ------------------- pooling + head -------------------
__global__ void k_pool(const float* __restrict__ h, const float* __restrict__ Wout,
                       const float* __restrict__ bout, float* __restrict__ out) {
    int g = (blockIdx.x * blockDim.x + threadIdx.x) >> 5;
    int lid = threadIdx.x & 31;
    if (g >= GG) return;
    long long gs = (long long)g * NN;
    int start = (int)((gs + GG - 1) / GG);
    int end = (int)((gs + NN + GG - 1) / GG);
    if (end > NN) end = NN;
    const float2* h2 = (const float2*)h;
    float2 mx = make_float2(-INFINITY, -INFINITY);
    float2 sm = make_float2(0.f, 0.f);
    for (int i = start; i < end; i++) {
        float2 v = h2[i * 32 + lid];
        mx.x = fmaxf(mx.x, v.x);
        mx.y = fmaxf(mx.y, v.y);
        sm.x += v.x;
        sm.y += v.y;
    }
    int cnt = end - start; if (cnt < 1) cnt = 1;
    float inv = 1.0f / (float)cnt;
    const float2* w2 = (const float2*)Wout;
    float2 wmx = w2[lid];
    float2 wmn = w2[32 + lid];
    float v = mx.x * wmx.x + mx.y * wmx.y
            + (sm.x * inv) * wmn.x + (sm.y * inv) * wmn.y;
#pragma unroll
    for (int o = 16; o; o >>= 1) v += __shfl_down_sync(0xffffffffu, v, o);
    if (lid == 0) out[g] = v + bout[0];
}

// ------------------- launch -------------------

extern "C" void kernel_launch(void* const* d_in, const int* in_sizes, int n_in,
                              void* d_out, int out_size) {
    const float* x    = (const float*)d_in[0];
    const int*   ei   = (const int*)d_in[1];
    const float* W0   = (const float*)d_in[3];
    const float* b0   = (const float*)d_in[4];
    const float* W1   = (const float*)d_in[5];
    const float* b1   = (const float*)d_in[6];
    const float* W2   = (const float*)d_in[7];
    const float* b2   = (const float*)d_in[8];
    const float* W3   = (const float*)d_in[9];
    const float* b3   = (const float*)d_in[10];
    const float* Wout = (const float*)d_in[11];
    const float* bout = (const float*)d_in[12];
    float* out = (float*)d_out;

    const int* erow = ei;        // sources
    const int* ecol = ei + EE;   // destinations

    float *hA, *hB;
    cudaGetSymbolAddress((void**)&hA, g_hA);
    cudaGetSymbolAddress((void**)&hB, g_hB);

    int eB8 = (EE / 8 + 255) / 256;   // 391
    int gB = (NN + 63) / 64;          // 782
    int pB = (GG * 32 + 255) / 256;

    k_hist<<<eB8, 256>>>(ecol);
    k_scan<<<NBLK, 256>>>(x);
    k_fill<<<eB8, 256>>>(erow, ecol);

    k_layer0<<<gB, 512>>>(W0, b0, (__half2*)hA);
    k_layer<true, true><<<gB, 512>>>((const __half2*)hA, W1, b1, hB);
    k_layer<true, true><<<gB, 512>>>((const __half2*)hB, W2, b2, hA);
    k_layer<false, false><<<gB, 512>>>((const __half2*)hA, W3, b3, hB);

    k_pool<<<pB, 256>>>(hB, Wout, bout, out);
}

// round 13
// speedup vs baseline: 3.0280x; 1.0607x over previous
#include <cuda_runtime.h>
#include <cuda_fp16.h>
#include <math.h>

#define NN 50000
#define EE 800000
#define GG 1024
#define DD 64
#define DIN 9
#define NBLK ((NN + 255) / 256)    // 196

// ---- scratch ----
__device__ int   g_deg[NN];        // all-zero at entry; re-zeroed in k_fill each call
__device__ float g_dinv[NN];
__device__ int   g_rowptr[NN + 1];
__device__ int   g_cursor[NN];
__device__ int   g_csrsrc[EE];
__device__ unsigned long long g_blkDesc[NBLK];  // zeroed in k_hist each call
__device__ uint4 g_xs16[NN * 2];   // fp16 input features, 16 halves/node (9 used)
__device__ float g_hA[NN * DD];
__device__ float g_hB[NN * DD];

__device__ __forceinline__ float tanh_a(float x) {
    float y;
    asm("tanh.approx.f32 %0, %1;" : "=f"(y) : "f"(x));
    return y;
}
__device__ __forceinline__ unsigned int smem_u32(const void* p) {
    return (unsigned int)__cvta_generic_to_shared(p);
}
__device__ __forceinline__ void ldmx4(unsigned int& r0, unsigned int& r1,
                                      unsigned int& r2, unsigned int& r3, unsigned int a) {
    asm volatile("ldmatrix.sync.aligned.m8n8.x4.shared.b16 {%0,%1,%2,%3}, [%4];"
                 : "=r"(r0), "=r"(r1), "=r"(r2), "=r"(r3) : "r"(a));
}
__device__ __forceinline__ void ldmx4t(unsigned int& r0, unsigned int& r1,
                                       unsigned int& r2, unsigned int& r3, unsigned int a) {
    asm volatile("ldmatrix.sync.aligned.m8n8.x4.trans.shared.b16 {%0,%1,%2,%3}, [%4];"
                 : "=r"(r0), "=r"(r1), "=r"(r2), "=r"(r3) : "r"(a));
}
__device__ __forceinline__ void mma16816(float* c, unsigned int a0, unsigned int a1,
                                         unsigned int a2, unsigned int a3,
                                         unsigned int b0, unsigned int b1) {
    asm volatile("mma.sync.aligned.m16n8k16.row.col.f32.f16.f16.f32 "
                 "{%0,%1,%2,%3}, {%4,%5,%6,%7}, {%8,%9}, {%0,%1,%2,%3};"
                 : "+f"(c[0]), "+f"(c[1]), "+f"(c[2]), "+f"(c[3])
                 : "r"(a0), "r"(a1), "r"(a2), "r"(a3), "r"(b0), "r"(b1));
}

#define H2C(p) (*(const __half2*)&(p))

// ------------------- preprocessing -------------------

__global__ void k_hist(const int* __restrict__ col) {
    int i = blockIdx.x * blockDim.x + threadIdx.x;
    if (i < NBLK) g_blkDesc[i] = 0ULL;
    long long base = (long long)i * 8;
    if (base < EE) {
        int4 a = reinterpret_cast<const int4*>(col)[i * 2];
        int4 b = reinterpret_cast<const int4*>(col)[i * 2 + 1];
        atomicAdd(&g_deg[a.x], 1); atomicAdd(&g_deg[a.y], 1);
        atomicAdd(&g_deg[a.z], 1); atomicAdd(&g_deg[a.w], 1);
        atomicAdd(&g_deg[b.x], 1); atomicAdd(&g_deg[b.y], 1);
        atomicAdd(&g_deg[b.z], 1); atomicAdd(&g_deg[b.w], 1);
    }
}

__global__ void k_scan(const float* __restrict__ x) {
    __shared__ int wsum[8];
    __shared__ int sprefix;
    int b = blockIdx.x, t = threadIdx.x;
    int i = b * 256 + t;
    int lane = t & 31, w = t >> 5;
    int v = (i < NN) ? g_deg[i] : 0;
    int s = v;
#pragma unroll
    for (int o = 1; o < 32; o <<= 1) {
        int u = __shfl_up_sync(~0u, s, o);
        if (lane >= o) s += u;
    }
    if (lane == 31) wsum[w] = s;
    __syncthreads();
    if (w == 0) {
        int ws = (lane < 8) ? wsum[lane] : 0;
#pragma unroll
        for (int o = 1; o < 8; o <<= 1) {
            int u = __shfl_up_sync(0xffu, ws, o);
            if (lane >= o) ws += u;
        }
        if (lane < 8) wsum[lane] = ws;
    }
    __syncthreads();
    int total = wsum[7];
    if (t == 0) {
        if (b == 0) {
            atomicExch(&g_blkDesc[0], ((unsigned long long)total << 2) | 2ULL);
            sprefix = 0;
        } else {
            atomicExch(&g_blkDesc[b], ((unsigned long long)total << 2) | 1ULL);
            int run = 0;
            for (int j = b - 1; j >= 0; j--) {
                unsigned long long d;
                do { d = *((volatile unsigned long long*)&g_blkDesc[j]); } while ((d & 3ULL) == 0ULL);
                run += (int)(d >> 2);
                if ((d & 3ULL) == 2ULL) break;
            }
            sprefix = run;
            atomicExch(&g_blkDesc[b], ((unsigned long long)(total + run) << 2) | 2ULL);
        }
    }
    __syncthreads();
    int excl = sprefix + (w > 0 ? wsum[w - 1] : 0) + (s - v);
    if (i < NN) {
        g_rowptr[i] = excl;
        g_cursor[i] = excl;
        float di = rsqrtf((float)v + 1.0f);  // +1 self loop
        g_dinv[i] = di;
        __half2* xo = (__half2*)g_xs16;
        float f[10];
#pragma unroll
        for (int c = 0; c < DIN; c++) f[c] = di * x[i * DIN + c];
        f[9] = 0.f;
#pragma unroll
        for (int j = 0; j < 5; j++)
            xo[i * 8 + j] = __floats2half2_rn(f[2 * j], f[2 * j + 1]);
#pragma unroll
        for (int j = 5; j < 8; j++)
            xo[i * 8 + j] = __floats2half2_rn(0.f, 0.f);
    }
    if (i == 0) g_rowptr[NN] = EE;
}

__global__ void k_fill(const int* __restrict__ row, const int* __restrict__ col) {
    int i = blockIdx.x * blockDim.x + threadIdx.x;
    if (i < NN) g_deg[i] = 0;
    long long base = (long long)i * 8;
    if (base < EE) {
        int4 ra = reinterpret_cast<const int4*>(row)[i * 2];
        int4 rb = reinterpret_cast<const int4*>(row)[i * 2 + 1];
        int4 ca = reinterpret_cast<const int4*>(col)[i * 2];
        int4 cb = reinterpret_cast<const int4*>(col)[i * 2 + 1];
        g_csrsrc[atomicAdd(&g_cursor[ca.x], 1)] = ra.x;
        g_csrsrc[atomicAdd(&g_cursor[ca.y], 1)] = ra.y;
        g_csrsrc[atomicAdd(&g_cursor[ca.z], 1)] = ra.z;
        g_csrsrc[atomicAdd(&g_cursor[ca.w], 1)] = ra.w;
        g_csrsrc[atomicAdd(&g_cursor[cb.x], 1)] = rb.x;
        g_csrsrc[atomicAdd(&g_cursor[cb.y], 1)] = rb.y;
        g_csrsrc[atomicAdd(&g_cursor[cb.z], 1)] = rb.z;
        g_csrsrc[atomicAdd(&g_cursor[cb.w], 1)] = rb.w;
    }
}

// fp32-path accumulate: 8 half cols from a uint4 into a0..a7
#define ACC8(q)                                                              \
    { float2 f;                                                              \
      f = __half22float2(H2C((q).x)); a0 += f.x; a1 += f.y;                  \
      f = __half22float2(H2C((q).y)); a2 += f.x; a3 += f.y;                  \
      f = __half22float2(H2C((q).z)); a4 += f.x; a5 += f.y;                  \
      f = __half22float2(H2C((q).w)); a6 += f.x; a7 += f.y; }

// same into named accumulator array
#define ACC8V(acc, q)                                                        \
    { float2 f;                                                              \
      f = __half22float2(H2C((q).x)); acc[0] += f.x; acc[1] += f.y;          \
      f = __half22float2(H2C((q).y)); acc[2] += f.x; acc[3] += f.y;          \
      f = __half22float2(H2C((q).z)); acc[4] += f.x; acc[5] += f.y;          \
      f = __half22float2(H2C((q).w)); acc[6] += f.x; acc[7] += f.y; }

// fp16 tree (q0+q1)+(q2+q3) then flush to fp32 accumulators
#define ACCTREE4(q0, q1, q2, q3)                                             \
    { __half2 t0 = __hadd2(H2C((q0).x), H2C((q1).x));                        \
      __half2 t1 = __hadd2(H2C((q0).y), H2C((q1).y));                        \
      __half2 t2 = __hadd2(H2C((q0).z), H2C((q1).z));                        \
      __half2 t3 = __hadd2(H2C((q0).w), H2C((q1).w));                        \
      __half2 u0 = __hadd2(H2C((q2).x), H2C((q3).x));                        \
      __half2 u1 = __hadd2(H2C((q2).y), H2C((q3).y));                        \
      __half2 u2 = __hadd2(H2C((q2).z), H2C((q3).z));                        \
      __half2 u3 = __hadd2(H2C((q2).w), H2C((q3).w));                        \
      __half2 v0 = __hadd2(t0, u0);                                          \
      __half2 v1 = __hadd2(t1, u1);                                          \
      __half2 v2 = __hadd2(t2, u2);                                          \
      __half2 v3 = __hadd2(t3, u3);                                          \
      float2 f;                                                              \
      f = __half22float2(v0); a0 += f.x; a1 += f.y;                          \
      f = __half22float2(v1); a2 += f.x; a3 += f.y;                          \
      f = __half22float2(v2); a4 += f.x; a5 += f.y;                          \
      f = __half22float2(v3); a6 += f.x; a7 += f.y; }

// ------------------- fused layer 0: 2-node interleaved predicated gather + FFMA GEMM -------------------

__global__ void __launch_bounds__(512) k_layer0(const float* __restrict__ W0,
                                                const float* __restrict__ b0,
                                                __half2* __restrict__ uout) {
    __shared__ float sW[DIN * DD];
    __shared__ float sHT[16][68];   // [feature][node]
    __shared__ float sB[DD];
    __shared__ float sDI[64];
    int tid = threadIdx.x;
    int nodeBase = blockIdx.x * 64;
    for (int i = tid; i < DIN * DD; i += 512) sW[i] = W0[i];
    if (tid < DD) sB[tid] = b0[tid];
    int unit = tid >> 4;     // 0..31, each handles nodes 2*unit, 2*unit+1
    int sl = tid & 15;
    int g = sl >> 1;         // neighbor slot 0..7
    int c2 = sl & 1;         // which uint4 of the 32B row
    const uint4* xs4 = (const uint4*)g_xs16;

    int locA = unit * 2, locB = unit * 2 + 1;
    int nodeA = nodeBase + locA, nodeB = nodeBase + locB;
    float accA[8] = {0, 0, 0, 0, 0, 0, 0, 0};
    float accB[8] = {0, 0, 0, 0, 0, 0, 0, 0};
    float diA = 0.f, diB = 0.f;
    int eA = 0, eA1 = 0, eB = 0, eB1 = 0;
    if (nodeA < NN) { diA = g_dinv[nodeA]; eA = g_rowptr[nodeA]; eA1 = g_rowptr[nodeA + 1]; }
    if (nodeB < NN) { diB = g_dinv[nodeB]; eB = g_rowptr[nodeB]; eB1 = g_rowptr[nodeB + 1]; }
    eA += g; eB += g;
    while (eA < eA1 || eB < eB1) {
        if (eA < eA1) { uint4 q = xs4[g_csrsrc[eA] * 2 + c2]; ACC8V(accA, q); }
        if (eB < eB1) { uint4 q = xs4[g_csrsrc[eB] * 2 + c2]; ACC8V(accB, q); }
        eA += 8; eB += 8;
    }
    // merge 8 neighbor slots within the 16-lane unit (same c2 parity)
#pragma unroll
    for (int o = 8; o >= 2; o >>= 1) {
#pragma unroll
        for (int j = 0; j < 8; j++) {
            accA[j] += __shfl_down_sync(~0u, accA[j], o, 16);
            accB[j] += __shfl_down_sync(~0u, accB[j], o, 16);
        }
    }
    if (sl < 2) {  // sl == c2
        if (nodeA < NN) {
            uint4 qs = xs4[nodeA * 2 + sl];
            float2 f;
            f = __half22float2(H2C(qs.x)); accA[0] = diA * (accA[0] + f.x); accA[1] = diA * (accA[1] + f.y);
            f = __half22float2(H2C(qs.y)); accA[2] = diA * (accA[2] + f.x); accA[3] = diA * (accA[3] + f.y);
            f = __half22float2(H2C(qs.z)); accA[4] = diA * (accA[4] + f.x); accA[5] = diA * (accA[5] + f.y);
            f = __half22float2(H2C(qs.w)); accA[6] = diA * (accA[6] + f.x); accA[7] = diA * (accA[7] + f.y);
        }
        if (nodeB < NN) {
            uint4 qs = xs4[nodeB * 2 + sl];
            float2 f;
            f = __half22float2(H2C(qs.x)); accB[0] = diB * (accB[0] + f.x); accB[1] = diB * (accB[1] + f.y);
            f = __half22float2(H2C(qs.y)); accB[2] = diB * (accB[2] + f.x); accB[3] = diB * (accB[3] + f.y);
            f = __half22float2(H2C(qs.z)); accB[4] = diB * (accB[4] + f.x); accB[5] = diB * (accB[5] + f.y);
            f = __half22float2(H2C(qs.w)); accB[6] = diB * (accB[6] + f.x); accB[7] = diB * (accB[7] + f.y);
        }
#pragma unroll
        for (int j = 0; j < 8; j++) {
            sHT[8 * sl + j][locA] = accA[j];
            sHT[8 * sl + j][locB] = accB[j];
        }
        if (sl == 0) { sDI[locA] = diA; sDI[locB] = diB; }
    }
    __syncthreads();
    int dq = tid & 31, nq = tid >> 5;
    float acc[4][2];
#pragma unroll
    for (int i = 0; i < 4; i++) { acc[i][0] = sB[2 * dq]; acc[i][1] = sB[2 * dq + 1]; }
#pragma unroll
    for (int k = 0; k < DIN; k++) {
        float4 h4 = *reinterpret_cast<const float4*>(&sHT[k][4 * nq]);
        float2 w2 = *reinterpret_cast<const float2*>(&sW[k * DD + 2 * dq]);
        acc[0][0] += h4.x * w2.x; acc[0][1] += h4.x * w2.y;
        acc[1][0] += h4.y * w2.x; acc[1][1] += h4.y * w2.y;
        acc[2][0] += h4.z * w2.x; acc[2][1] += h4.z * w2.y;
        acc[3][0] += h4.w * w2.x; acc[3][1] += h4.w * w2.y;
    }
#pragma unroll
    for (int i = 0; i < 4; i++) {
        int n = nodeBase + 4 * nq + i;
        if (n < NN) {
            float sc = sDI[4 * nq + i];
            uout[n * 32 + dq] = __floats2half2_rn(sc * tanh_a(acc[i][0]),
                                                  sc * tanh_a(acc[i][1]));
        }
    }
}

// ------------------- fused layer: scalar-index fp16-tree gather + fp16 MMA GEMM -------------------

template <bool OUT_HALF, bool PRESCALE>
__global__ void __launch_bounds__(512) k_layer(const __half2* __restrict__ uin,
                                               const float* __restrict__ W,
                                               const float* __restrict__ bias,
                                               void* __restrict__ uout) {
    __shared__ __half sA[64][72];    // agg tile fp16, stride 72 (ldmatrix conflict-free)
    __shared__ __half sBW[64][72];   // W fp16 [k][col]
    __shared__ float  sB[DD];
    __shared__ float  sDI[64];
    int tid = threadIdx.x;
    int nodeBase = blockIdx.x * 64;
    for (int i = tid; i < DD * DD; i += 512)
        sBW[i >> 6][i & 63] = __float2half(W[i]);
    if (tid < DD) sB[tid] = bias[tid];
    int w = tid >> 5, lid = tid & 31;
    int hw = lid >> 4;      // node of pair
    int sl = lid & 15;
    int g8 = sl >> 3;       // neighbor slot (0/1)
    int c8 = sl & 7;        // uint4 col (half-cols 8c8..8c8+7)
    const uint4* u4 = (const uint4*)uin;
#pragma unroll
    for (int pass = 0; pass < 2; pass++) {
        int local = w * 4 + pass * 2 + hw;
        int node = nodeBase + local;
        float a0 = 0.f, a1 = 0.f, a2 = 0.f, a3 = 0.f;
        float a4 = 0.f, a5 = 0.f, a6 = 0.f, a7 = 0.f;
        float di = 0.f;
        if (node < NN) {
            di = g_dinv[node];
            int e = g_rowptr[node], e1 = g_rowptr[node + 1];
            // 8 edges per iter, scalar (coalesced) index loads, no alignment needed
            for (; e + 8 <= e1; e += 8) {
                int s0 = g_csrsrc[e + g8];
                int s1 = g_csrsrc[e + 2 + g8];
                int s2 = g_csrsrc[e + 4 + g8];
                int s3 = g_csrsrc[e + 6 + g8];
                uint4 q0 = u4[s0 * 8 + c8];
                uint4 q1 = u4[s1 * 8 + c8];
                uint4 q2 = u4[s2 * 8 + c8];
                uint4 q3 = u4[s3 * 8 + c8];
                ACCTREE4(q0, q1, q2, q3);
            }
            // predicated tail: each lane group covers its parity
            for (int e2 = e + g8; e2 < e1; e2 += 2) {
                uint4 q = u4[g_csrsrc[e2] * 8 + c8]; ACC8(q);
            }
        }
        // merge the two neighbor-slot groups
        a0 += __shfl_down_sync(~0u, a0, 8, 16);
        a1 += __shfl_down_sync(~0u, a1, 8, 16);
        a2 += __shfl_down_sync(~0u, a2, 8, 16);
        a3 += __shfl_down_sync(~0u, a3, 8, 16);
        a4 += __shfl_down_sync(~0u, a4, 8, 16);
        a5 += __shfl_down_sync(~0u, a5, 8, 16);
        a6 += __shfl_down_sync(~0u, a6, 8, 16);
        a7 += __shfl_down_sync(~0u, a7, 8, 16);
        if (sl < 8) {
            if (node < NN) {
                uint4 qs = u4[node * 8 + c8];
                float2 f;
                f = __half22float2(H2C(qs.x)); a0 = di * (a0 + f.x); a1 = di * (a1 + f.y);
                f = __half22float2(H2C(qs.y)); a2 = di * (a2 + f.x); a3 = di * (a3 + f.y);
                f = __half22float2(H2C(qs.z)); a4 = di * (a4 + f.x); a5 = di * (a5 + f.y);
                f = __half22float2(H2C(qs.w)); a6 = di * (a6 + f.x); a7 = di * (a7 + f.y);
            }
            __half2 h0 = __floats2half2_rn(a0, a1);
            __half2 h1 = __floats2half2_rn(a2, a3);
            __half2 h2 = __floats2half2_rn(a4, a5);
            __half2 h3 = __floats2half2_rn(a6, a7);
            uint4 q;
            q.x = *reinterpret_cast<unsigned int*>(&h0);
            q.y = *reinterpret_cast<unsigned int*>(&h1);
            q.z = *reinterpret_cast<unsigned int*>(&h2);
            q.w = *reinterpret_cast<unsigned int*>(&h3);
            *reinterpret_cast<uint4*>(&sA[local][c8 * 8]) = q;
            if (c8 == 0) sDI[local] = di;
        }
    }
    __syncthreads();
    // MMA: warp (mi,ni) computes nodes 16mi..16mi+15 x cols 16ni..16ni+15
    int lane = tid & 31;
    int wid = tid >> 5;
    int mi = wid >> 2, ni = wid & 3;
    float c0[4] = {0.f, 0.f, 0.f, 0.f};
    float c1[4] = {0.f, 0.f, 0.f, 0.f};
    unsigned int aBase = smem_u32(&sA[16 * mi + (lane & 15)][(lane >> 4) * 8]);
    unsigned int bBase = smem_u32(&sBW[lane & 15][16 * ni + ((lane >> 4) << 3)]);
#pragma unroll
    for (int kk = 0; kk < 4; kk++) {
        unsigned int a0, a1, a2, a3, b0, b1, b2, b3;
        ldmx4(a0, a1, a2, a3, aBase + kk * 32);          // +16 halves in k
        ldmx4t(b0, b1, b2, b3, bBase + kk * 16 * 144);   // +16 rows of 144 B
        mma16816(c0, a0, a1, a2, a3, b0, b1);
        mma16816(c1, a0, a1, a2, a3, b2, b3);
    }
    int r0 = 16 * mi + (lane >> 2);
    int cb0 = 16 * ni + (lane & 3) * 2;
#pragma unroll
    for (int t2 = 0; t2 < 2; t2++) {
        const float* cc = t2 ? c1 : c0;
        int cb = cb0 + t2 * 8;
        float bx = sB[cb], by = sB[cb + 1];
#pragma unroll
        for (int rh = 0; rh < 2; rh++) {
            int r = r0 + rh * 8;
            int n = nodeBase + r;
            if (n < NN) {
                float v0 = cc[2 * rh] + bx;
                float v1 = cc[2 * rh + 1] + by;
                if (OUT_HALF) {
                    float sc = PRESCALE ? sDI[r] : 1.0f;
                    ((__half2*)uout)[n * 32 + (cb >> 1)] =
                        __floats2half2_rn(sc * tanh_a(v0), sc * tanh_a(v1));
                } else {
                    ((float2*)uout)[n * 32 + (cb >> 1)] =
                        make_float2(tanh_a(v0), tanh_a(v1));
                }
            }
        }
    }
}

// ------------------- pooling + head -------------------
__global__ void k_pool(const float* __restrict__ h, const float* __restrict__ Wout,
                       const float* __restrict__ bout, float* __restrict__ out) {
    int g = (blockIdx.x * blockDim.x + threadIdx.x) >> 5;
    int lid = threadIdx.x & 31;
    if (g >= GG) return;
    long long gs = (long long)g * NN;
    int start = (int)((gs + GG - 1) / GG);
    int end = (int)((gs + NN + GG - 1) / GG);
    if (end > NN) end = NN;
    const float2* h2 = (const float2*)h;
    float2 mx = make_float2(-INFINITY, -INFINITY);
    float2 sm = make_float2(0.f, 0.f);
    for (int i = start; i < end; i++) {
        float2 v = h2[i * 32 + lid];
        mx.x = fmaxf(mx.x, v.x);
        mx.y = fmaxf(mx.y, v.y);
        sm.x += v.x;
        sm.y += v.y;
    }
    int cnt = end - start; if (cnt < 1) cnt = 1;
    float inv = 1.0f / (float)cnt;
    const float2* w2 = (const float2*)Wout;
    float2 wmx = w2[lid];
    float2 wmn = w2[32 + lid];
    float v = mx.x * wmx.x + mx.y * wmx.y
            + (sm.x * inv) * wmn.x + (sm.y * inv) * wmn.y;
#pragma unroll
    for (int o = 16; o; o >>= 1) v += __shfl_down_sync(0xffffffffu, v, o);
    if (lid == 0) out[g] = v + bout[0];
}

// ------------------- launch -------------------

extern "C" void kernel_launch(void* const* d_in, const int* in_sizes, int n_in,
                              void* d_out, int out_size) {
    const float* x    = (const float*)d_in[0];
    const int*   ei   = (const int*)d_in[1];
    const float* W0   = (const float*)d_in[3];
    const float* b0   = (const float*)d_in[4];
    const float* W1   = (const float*)d_in[5];
    const float* b1   = (const float*)d_in[6];
    const float* W2   = (const float*)d_in[7];
    const float* b2   = (const float*)d_in[8];
    const float* W3   = (const float*)d_in[9];
    const float* b3   = (const float*)d_in[10];
    const float* Wout = (const float*)d_in[11];
    const float* bout = (const float*)d_in[12];
    float* out = (float*)d_out;

    const int* erow = ei;        // sources
    const int* ecol = ei + EE;   // destinations

    float *hA, *hB;
    cudaGetSymbolAddress((void**)&hA, g_hA);
    cudaGetSymbolAddress((void**)&hB, g_hB);

    int eB8 = (EE / 8 + 255) / 256;   // 391
    int gB = (NN + 63) / 64;          // 782
    int pB = (GG * 32 + 255) / 256;

    k_hist<<<eB8, 256>>>(ecol);
    k_scan<<<NBLK, 256>>>(x);
    k_fill<<<eB8, 256>>>(erow, ecol);

    k_layer0<<<gB, 512>>>(W0, b0, (__half2*)hA);
    k_layer<true, true><<<gB, 512>>>((const __half2*)hA, W1, b1, hB);
    k_layer<true, true><<<gB, 512>>>((const __half2*)hB, W2, b2, hA);
    k_layer<false, false><<<gB, 512>>>((const __half2*)hA, W3, b3, hB);

    k_pool<<<pB, 256>>>(hB, Wout, bout, out);
}